// round 10
// baseline (speedup 1.0000x reference)
#include <cuda_runtime.h>
#include <cuda_bf16.h>
#include <cstdint>

#define NSEQ 1024
#define DIM  256
#define HEADS 8
#define EDIM 512
#define HD   64
#define PEC  32
#define BH   32           // B*HEADS
#define ROWS 4096         // B*N

// ---------------- scratch (device globals; no runtime allocation) ----------
__device__ __nv_bfloat16 g_xh[ROWS * DIM], g_xl[ROWS * DIM];
__device__ __nv_bfloat16 g_wth[1536 * 256], g_wtl[1536 * 256];   // [n][k]
__device__ __nv_bfloat16 g_wpth[256 * 512], g_wptl[256 * 512];   // [n][k]
__device__ __nv_bfloat16 g_qh[BH * NSEQ * HD];
__device__ __nv_bfloat16 g_ql[BH * NSEQ * HD];
__device__ __nv_bfloat16 g_kh[BH * NSEQ * HD];
__device__ __nv_bfloat16 g_kl[BH * NSEQ * HD];
__device__ __nv_bfloat16 g_vth[BH * HD * NSEQ];   // transposed: [bh][d][n]
__device__ __nv_bfloat16 g_vtl[BH * HD * NSEQ];
__device__ __nv_bfloat16 g_attn_h[(size_t)BH * NSEQ * NSEQ];  // 64 MB
__device__ __nv_bfloat16 g_attn_l[(size_t)BH * NSEQ * NSEQ];  // 64 MB
__device__ float g_oh[BH * NSEQ * HD];
__device__ float g_pes[BH * NSEQ * PEC];
__device__ __nv_bfloat16 g_mh[ROWS * EDIM], g_ml[ROWS * EDIM];

union B16x8 { __nv_bfloat16 h[8]; uint4 u; };
union B16x4 { __nv_bfloat16 h[4]; uint2 u; };
union B16x2 { __nv_bfloat16 h[2]; uint32_t u; };

__device__ __forceinline__ void split2(float x, __nv_bfloat16& h, __nv_bfloat16& l) {
  h = __float2bfloat16_rn(x);
  l = __float2bfloat16_rn(x - __bfloat162float(h));
}

// m16n8k16 bf16 mma with fp32 accumulate (row.col)
__device__ __forceinline__ void mma16816(float* c, const uint32_t* a,
                                         const uint32_t* b) {
  asm volatile(
      "mma.sync.aligned.m16n8k16.row.col.f32.bf16.bf16.f32 "
      "{%0,%1,%2,%3}, {%4,%5,%6,%7}, {%8,%9}, {%0,%1,%2,%3};"
      : "+f"(c[0]), "+f"(c[1]), "+f"(c[2]), "+f"(c[3])
      : "r"(a[0]), "r"(a[1]), "r"(a[2]), "r"(a[3]), "r"(b[0]), "r"(b[1]));
}

// ldmatrix x4: 4 8x8 b16 tiles; lane group g=lane>>3 supplies address of tile g
__device__ __forceinline__ void ldsm4(uint32_t* d, const __nv_bfloat16* p) {
  uint32_t a = (uint32_t)__cvta_generic_to_shared(p);
  asm volatile("ldmatrix.sync.aligned.m8n8.x4.shared.b16 {%0,%1,%2,%3}, [%4];"
               : "=r"(d[0]), "=r"(d[1]), "=r"(d[2]), "=r"(d[3]) : "r"(a));
}

// 16B async copy gmem -> smem
__device__ __forceinline__ void cp16(__nv_bfloat16* smem_ptr, const __nv_bfloat16* gptr) {
  uint32_t s = (uint32_t)__cvta_generic_to_shared(smem_ptr);
  asm volatile("cp.async.cg.shared.global [%0], [%1], 16;" :: "r"(s), "l"(gptr));
}
#define CP_COMMIT() asm volatile("cp.async.commit_group;" ::: "memory")
#define CP_WAIT1()  asm volatile("cp.async.wait_group 1;" ::: "memory")
#define CP_WAIT0()  asm volatile("cp.async.wait_group 0;" ::: "memory")

#define LDSTRIDE 72   // bf16 units per SMEM row (64 data + 8 pad)
#define PSTRIDE 136   // bf16 units per SMEM row (128 data + 8 pad)
#define GEMM_SMEM_BYTES ((2 * 128 + 2 * 64) * LDSTRIDE * 2)   // 55296

// ---------------- prep: split x into bf16 hi/lo ------------------------------
__global__ __launch_bounds__(256) void split_x(const float* __restrict__ x) {
  int idx = (blockIdx.x * 256 + threadIdx.x) * 4;
  float4 v = *(const float4*)(x + idx);
  B16x4 hh, ll;
  split2(v.x, hh.h[0], ll.h[0]); split2(v.y, hh.h[1], ll.h[1]);
  split2(v.z, hh.h[2], ll.h[2]); split2(v.w, hh.h[3], ll.h[3]);
  *(uint2*)&g_xh[idx] = hh.u;
  *(uint2*)&g_xl[idx] = ll.u;
}

// ---------------- prep: transpose + split weights -----------------------------
__global__ __launch_bounds__(256) void prep_w(
    const float* __restrict__ Wq, const float* __restrict__ Wk,
    const float* __restrict__ Wv, const float* __restrict__ Wproj) {
  int id = blockIdx.x * 256 + threadIdx.x;
  if (id < 98304) {                 // WT: 1536 n x 64 k-groups
    int n = id >> 6, k0 = (id & 63) * 4;
    int sel = n >> 9, col = n & 511;
    const float* W = (sel == 0) ? Wq : (sel == 1) ? Wk : Wv;
#pragma unroll
    for (int q = 0; q < 4; q++) {
      float v = W[(k0 + q) * 512 + col];
      split2(v, g_wth[n * 256 + k0 + q], g_wtl[n * 256 + k0 + q]);
    }
  } else {                          // WprojT: 256 n x 128 k-groups
    int id2 = id - 98304;
    int n = id2 >> 7, k0 = (id2 & 127) * 4;
#pragma unroll
    for (int q = 0; q < 4; q++) {
      float v = Wproj[(k0 + q) * 256 + n];
      split2(v, g_wpth[n * 512 + k0 + q], g_wptl[n * 512 + k0 + q]);
    }
  }
}

// ---------------- Kernel 1: QKV projection via mma.sync ---------------------
// M=4096, N=1536, K=256. CTA 128m x 64n, grid (32, 24). 8 warps: 4m x 2n.
__global__ __launch_bounds__(256) void qkv_mma(const float* __restrict__ bv) {
  extern __shared__ __nv_bfloat16 sm[];
  __nv_bfloat16* XH = sm;
  __nv_bfloat16* XL = XH + 128 * LDSTRIDE;
  __nv_bfloat16* WH = XL + 128 * LDSTRIDE;
  __nv_bfloat16* WL = WH + 64 * LDSTRIDE;

  int tid = threadIdx.x;
  int wid = tid >> 5, lane = tid & 31;
  int m0 = blockIdx.x * 128;
  int n0 = blockIdx.y * 64;
  int sel = n0 / 512;
  int e0 = n0 % 512;
  int h = e0 / 64;

  int m_w = (wid >> 1) * 32, n_w = (wid & 1) * 32;
  int r = lane >> 2;
  int g = lane >> 3, rw = lane & 7;

  float c[2][4][4];
#pragma unroll
  for (int mt = 0; mt < 2; mt++)
#pragma unroll
    for (int nt = 0; nt < 4; nt++)
#pragma unroll
      for (int e = 0; e < 4; e++) c[mt][nt][e] = 0.f;

  for (int ck = 0; ck < 4; ck++) {
    if (ck) __syncthreads();
#pragma unroll
    for (int t = 0; t < 4; t++) {
      int idx = tid + 256 * t;
      int rr = idx >> 3, seg = idx & 7;
      int so = rr * LDSTRIDE + seg * 8;
      size_t gs = (size_t)(m0 + rr) * 256 + ck * 64 + seg * 8;
      *(uint4*)(XH + so) = *(const uint4*)(g_xh + gs);
      *(uint4*)(XL + so) = *(const uint4*)(g_xl + gs);
    }
#pragma unroll
    for (int t = 0; t < 2; t++) {
      int idx = tid + 256 * t;
      int d = idx >> 3, seg = idx & 7;
      int so = d * LDSTRIDE + seg * 8;
      size_t gs = (size_t)(n0 + d) * 256 + ck * 64 + seg * 8;
      *(uint4*)(WH + so) = *(const uint4*)(g_wth + gs);
      *(uint4*)(WL + so) = *(const uint4*)(g_wtl + gs);
    }
    __syncthreads();
#pragma unroll
    for (int kb = 0; kb < 64; kb += 16) {
      uint32_t ah[2][4], al[2][4];
#pragma unroll
      for (int mt = 0; mt < 2; mt++) {
        ldsm4(ah[mt], XH + (m_w + mt * 16 + (g & 1) * 8 + rw) * LDSTRIDE + kb + (g >> 1) * 8);
        ldsm4(al[mt], XL + (m_w + mt * 16 + (g & 1) * 8 + rw) * LDSTRIDE + kb + (g >> 1) * 8);
      }
      uint32_t bh4[2][4], bl4[2][4];
#pragma unroll
      for (int p = 0; p < 2; p++) {
        ldsm4(bh4[p], WH + (n_w + p * 16 + (g >> 1) * 8 + rw) * LDSTRIDE + kb + (g & 1) * 8);
        ldsm4(bl4[p], WL + (n_w + p * 16 + (g >> 1) * 8 + rw) * LDSTRIDE + kb + (g & 1) * 8);
      }
#pragma unroll
      for (int mt = 0; mt < 2; mt++)
#pragma unroll
        for (int p = 0; p < 2; p++) {
          mma16816(c[mt][2 * p], ah[mt], bh4[p]);
          mma16816(c[mt][2 * p], ah[mt], bl4[p]);
          mma16816(c[mt][2 * p], al[mt], bh4[p]);
          mma16816(c[mt][2 * p + 1], ah[mt], bh4[p] + 2);
          mma16816(c[mt][2 * p + 1], ah[mt], bl4[p] + 2);
          mma16816(c[mt][2 * p + 1], al[mt], bh4[p] + 2);
        }
    }
  }

#pragma unroll
  for (int mt = 0; mt < 2; mt++) {
#pragma unroll
    for (int nt = 0; nt < 4; nt++) {
      int colw = n_w + nt * 8 + (lane & 3) * 2;   // 0..62, even
      int d = colw;                                // channel within head
      int e = e0 + colw;
#pragma unroll
      for (int half = 0; half < 2; half++) {
        int row = m0 + m_w + mt * 16 + r + half * 8;
        float v0 = c[mt][nt][half * 2 + 0];
        float v1 = c[mt][nt][half * 2 + 1];
        int b = row >> 10, n = row & 1023;
        int bh = b * 8 + h;
        if (sel == 0) {
          v0 *= 0.125f; v1 *= 0.125f;
          B16x2 hp, lp;
          split2(v0, hp.h[0], lp.h[0]); split2(v1, hp.h[1], lp.h[1]);
          size_t idx = ((size_t)bh * 1024 + n) * 64 + d;
          *(uint32_t*)&g_qh[idx] = hp.u;
          *(uint32_t*)&g_ql[idx] = lp.u;
        } else if (sel == 1) {
          B16x2 hp, lp;
          split2(v0, hp.h[0], lp.h[0]); split2(v1, hp.h[1], lp.h[1]);
          size_t idx = ((size_t)bh * 1024 + n) * 64 + d;
          *(uint32_t*)&g_kh[idx] = hp.u;
          *(uint32_t*)&g_kl[idx] = lp.u;
        } else {
          v0 += bv[e]; v1 += bv[e + 1];
          __nv_bfloat16 hh, ll;
          split2(v0, hh, ll);
          size_t i0v = ((size_t)bh * 64 + d) * 1024 + n;
          g_vth[i0v] = hh; g_vtl[i0v] = ll;
          split2(v1, hh, ll);
          size_t i1v = ((size_t)bh * 64 + d + 1) * 1024 + n;
          g_vth[i1v] = hh; g_vtl[i1v] = ll;
        }
      }
    }
  }
}

// ---------------- Kernel 2: FUSED scores + softmax + attn@V -----------------
// Phase 1: scores (2-pass q hi/lo vs k hi), cp.async K pipeline, ldmatrix.
// Phase 2: softmax; write split attn to gmem (for pes); save packed A-frags.
// Phase 3: out = attn @ V with cp.async V pipeline (3-pass split).
// CTA = 32 query rows x FULL 1024 cols. grid (32, 32). 8 warps: 2m x 4n.
#define KSTAGE (128 * LDSTRIDE)     // 9216 elems per K stage
#define VSTAGE (64 * PSTRIDE)       // 8704 elems per V array per stage
#define FSM_Q (32 * LDSTRIDE)
#define FSM_SMEM_BYTES ((2 * FSM_Q + 2 * KSTAGE + 4 * VSTAGE) * 2)  // 115712
__global__ __launch_bounds__(256) void scoresm() {
  extern __shared__ __nv_bfloat16 smd[];
  __nv_bfloat16* QH = smd;
  __nv_bfloat16* QL = QH + FSM_Q;
  __nv_bfloat16* KHb = QL + FSM_Q;          // 2 stages of KSTAGE
  __nv_bfloat16* VHb = KHb + 2 * KSTAGE;    // 2 stages of (hi VSTAGE + lo VSTAGE)
  __shared__ float red[32][4];

  int tid = threadIdx.x;
  int wid = tid >> 5, lane = tid & 31;
  int bh = blockIdx.y;
  int i0 = blockIdx.x * 32;

  const __nv_bfloat16* qh = g_qh + (size_t)bh * NSEQ * HD;
  const __nv_bfloat16* ql = g_ql + (size_t)bh * NSEQ * HD;
  const __nv_bfloat16* kh = g_kh + (size_t)bh * NSEQ * HD;
  const __nv_bfloat16* vth = g_vth + (size_t)bh * HD * NSEQ;
  const __nv_bfloat16* vtl = g_vtl + (size_t)bh * HD * NSEQ;

  auto stage_v = [&](int jc, int s) {
    __nv_bfloat16* vh = VHb + s * 2 * VSTAGE;
    __nv_bfloat16* vl = vh + VSTAGE;
#pragma unroll
    for (int t = 0; t < 4; t++) {
      int idx = tid + 256 * t;            // 0..1023: 64 d-rows x 16 segs
      int d = idx >> 4, seg = idx & 15;
      int so = d * PSTRIDE + seg * 8;
      cp16(vh + so, vth + (size_t)d * 1024 + jc * 128 + seg * 8);
      cp16(vl + so, vtl + (size_t)d * 1024 + jc * 128 + seg * 8);
    }
  };

  // stage q (32 x 64, hi/lo): one uint4 per thread per array
  {
    int r = tid >> 3, seg = tid & 7;
    int so = r * LDSTRIDE + seg * 8;
    *(uint4*)(QH + so) = *(const uint4*)(qh + (i0 + r) * 64 + seg * 8);
    *(uint4*)(QL + so) = *(const uint4*)(ql + (i0 + r) * 64 + seg * 8);
  }
  // prefetch K chunk 0 and V chunk 0 in one group
#pragma unroll
  for (int t = 0; t < 4; t++) {
    int idx = tid + 256 * t;
    int rr = idx >> 3, seg = idx & 7;
    cp16(KHb + rr * LDSTRIDE + seg * 8, kh + rr * 64 + seg * 8);
  }
  stage_v(0, 0);
  CP_COMMIT();

  int mw = (wid & 1) * 16;
  int nwb = (wid >> 1) * 32;
  int r = lane >> 2;
  int g = lane >> 3, rw = lane & 7;

  uint32_t ah[4][4], al[4][4];
  float acc[8][4][4];
#pragma unroll
  for (int jc = 0; jc < 8; jc++)
#pragma unroll
    for (int nt = 0; nt < 4; nt++)
#pragma unroll
      for (int e = 0; e < 4; e++) acc[jc][nt][e] = 0.f;

  // ---------------- Phase 1: scores ----------------
#pragma unroll
  for (int jc = 0; jc < 8; jc++) {
    int st = jc & 1;
    if (jc < 7) {
      int sn = st ^ 1;
#pragma unroll
      for (int t = 0; t < 4; t++) {
        int idx = tid + 256 * t;
        int rr = idx >> 3, seg = idx & 7;
        cp16(KHb + sn * KSTAGE + rr * LDSTRIDE + seg * 8,
             kh + ((jc + 1) * 128 + rr) * 64 + seg * 8);
      }
      CP_COMMIT();
      CP_WAIT1();
    } else {
      CP_WAIT0();
    }
    __syncthreads();
    const __nv_bfloat16* KH = KHb + st * KSTAGE;
    if (jc == 0) {
#pragma unroll
      for (int kb = 0; kb < 4; kb++) {
        ldsm4(ah[kb], QH + (mw + (g & 1) * 8 + rw) * LDSTRIDE + kb * 16 + (g >> 1) * 8);
        ldsm4(al[kb], QL + (mw + (g & 1) * 8 + rw) * LDSTRIDE + kb * 16 + (g >> 1) * 8);
      }
    }
#pragma unroll
    for (int kb = 0; kb < 4; kb++) {
#pragma unroll
      for (int p = 0; p < 2; p++) {
        uint32_t b4[4];
        ldsm4(b4, KH + (nwb + p * 16 + (g >> 1) * 8 + rw) * LDSTRIDE + kb * 16 + (g & 1) * 8);
        mma16816(acc[jc][2 * p], ah[kb], b4);
        mma16816(acc[jc][2 * p], al[kb], b4);
        mma16816(acc[jc][2 * p + 1], ah[kb], b4 + 2);
        mma16816(acc[jc][2 * p + 1], al[kb], b4 + 2);
      }
    }
    __syncthreads();
  }

  // ---------------- Phase 2: softmax + attn store + frag save ----------------
  int r0 = mw + r, r1 = r0 + 8;
  float m0 = -1e30f, m1 = -1e30f;
#pragma unroll
  for (int jc = 0; jc < 8; jc++)
#pragma unroll
    for (int nt = 0; nt < 4; nt++) {
      m0 = fmaxf(m0, fmaxf(acc[jc][nt][0], acc[jc][nt][1]));
      m1 = fmaxf(m1, fmaxf(acc[jc][nt][2], acc[jc][nt][3]));
    }
#pragma unroll
  for (int o = 1; o <= 2; o <<= 1) {
    m0 = fmaxf(m0, __shfl_xor_sync(~0u, m0, o));
    m1 = fmaxf(m1, __shfl_xor_sync(~0u, m1, o));
  }
  if ((lane & 3) == 0) { red[r0][wid >> 1] = m0; red[r1][wid >> 1] = m1; }
  __syncthreads();
  m0 = fmaxf(fmaxf(red[r0][0], red[r0][1]), fmaxf(red[r0][2], red[r0][3]));
  m1 = fmaxf(fmaxf(red[r1][0], red[r1][1]), fmaxf(red[r1][2], red[r1][3]));
  __syncthreads();

  float s0 = 0.f, s1 = 0.f;
#pragma unroll
  for (int jc = 0; jc < 8; jc++)
#pragma unroll
    for (int nt = 0; nt < 4; nt++) {
      acc[jc][nt][0] = __expf(acc[jc][nt][0] - m0);
      acc[jc][nt][1] = __expf(acc[jc][nt][1] - m0);
      acc[jc][nt][2] = __expf(acc[jc][nt][2] - m1);
      acc[jc][nt][3] = __expf(acc[jc][nt][3] - m1);
      s0 += acc[jc][nt][0] + acc[jc][nt][1];
      s1 += acc[jc][nt][2] + acc[jc][nt][3];
    }
#pragma unroll
  for (int o = 1; o <= 2; o <<= 1) {
    s0 += __shfl_xor_sync(~0u, s0, o);
    s1 += __shfl_xor_sync(~0u, s1, o);
  }
  if ((lane & 3) == 0) { red[r0][wid >> 1] = s0; red[r1][wid >> 1] = s1; }
  __syncthreads();
  s0 = red[r0][0] + red[r0][1] + red[r0][2] + red[r0][3];
  s1 = red[r1][0] + red[r1][1] + red[r1][2] + red[r1][3];
  float inv0 = 1.f / s0, inv1 = 1.f / s1;

  // prefetch V chunk 1 so it flies behind the epilogue stores
  stage_v(1, 1);
  CP_COMMIT();

  uint32_t uah[8][4][2], ual[8][4][2];
  size_t base0 = (((size_t)bh << 10) + (i0 + r0)) << 10;
  size_t base1 = (((size_t)bh << 10) + (i0 + r1)) << 10;
#pragma unroll
  for (int jc = 0; jc < 8; jc++) {
#pragma unroll
    for (int nt = 0; nt < 4; nt++) {
      int col = jc * 128 + nwb + nt * 8 + (lane & 3) * 2;
      float e0 = acc[jc][nt][0] * inv0, e1 = acc[jc][nt][1] * inv0;
      float e2 = acc[jc][nt][2] * inv1, e3 = acc[jc][nt][3] * inv1;
      B16x2 hp, lp;
      split2(e0, hp.h[0], lp.h[0]); split2(e1, hp.h[1], lp.h[1]);
      *(uint32_t*)(g_attn_h + base0 + col) = hp.u;
      *(uint32_t*)(g_attn_l + base0 + col) = lp.u;
      uah[jc][nt][0] = hp.u; ual[jc][nt][0] = lp.u;
      split2(e2, hp.h[0], lp.h[0]); split2(e3, hp.h[1], lp.h[1]);
      *(uint32_t*)(g_attn_h + base1 + col) = hp.u;
      *(uint32_t*)(g_attn_l + base1 + col) = lp.u;
      uah[jc][nt][1] = hp.u; ual[jc][nt][1] = lp.u;
    }
  }

  // ---------------- Phase 3: out = attn @ V ----------------
  // Warp covers rows (mw..mw+15), k-slice cols {jc*128 + nwb + 0..31}.
  float o[8][4];
#pragma unroll
  for (int dt = 0; dt < 8; dt++)
#pragma unroll
    for (int e = 0; e < 4; e++) o[dt][e] = 0.f;

  for (int jc = 0; jc < 8; jc++) {
    int st = jc & 1;
    if (jc >= 1 && jc < 7) { stage_v(jc + 1, (jc + 1) & 1); CP_COMMIT(); }
    if (jc < 7) CP_WAIT1(); else CP_WAIT0();
    __syncthreads();
    const __nv_bfloat16* VH = VHb + st * 2 * VSTAGE;
    const __nv_bfloat16* VL = VH + VSTAGE;
#pragma unroll
    for (int np = 0; np < 2; np++) {
      uint32_t af[4]  = {uah[jc][2 * np][0], uah[jc][2 * np][1],
                         uah[jc][2 * np + 1][0], uah[jc][2 * np + 1][1]};
      uint32_t afl[4] = {ual[jc][2 * np][0], ual[jc][2 * np][1],
                         ual[jc][2 * np + 1][0], ual[jc][2 * np + 1][1]};
      int colb = nwb + np * 16;
#pragma unroll
      for (int p = 0; p < 4; p++) {
        uint32_t bh4[4], bl4[4];
        ldsm4(bh4, VH + (p * 16 + (g >> 1) * 8 + rw) * PSTRIDE + colb + (g & 1) * 8);
        ldsm4(bl4, VL + (p * 16 + (g >> 1) * 8 + rw) * PSTRIDE + colb + (g & 1) * 8);
        mma16816(o[2 * p], af, bh4);
        mma16816(o[2 * p], af, bl4);
        mma16816(o[2 * p], afl, bh4);
        mma16816(o[2 * p + 1], af, bh4 + 2);
        mma16816(o[2 * p + 1], af, bl4 + 2);
        mma16816(o[2 * p + 1], afl, bh4 + 2);
      }
    }
    __syncthreads();
  }

  // cross-warp k-reduction over the 4 n-warp groups (reuse dead K buffers)
  float* rbuf = (float*)KHb;     // 32 x 68 floats = 8704 B (< 36 KB K region)
#pragma unroll 1
  for (int p = 0; p < 4; p++) {
    if ((wid >> 1) == p) {
#pragma unroll
      for (int dt = 0; dt < 8; dt++) {
        int d0 = dt * 8 + (lane & 3) * 2;
        float* p0 = &rbuf[(size_t)(mw + r) * 68 + d0];
        float* p1 = &rbuf[(size_t)(mw + r + 8) * 68 + d0];
        if (p == 0) {
          p0[0] = o[dt][0]; p0[1] = o[dt][1];
          p1[0] = o[dt][2]; p1[1] = o[dt][3];
        } else {
          p0[0] += o[dt][0]; p0[1] += o[dt][1];
          p1[0] += o[dt][2]; p1[1] += o[dt][3];
        }
      }
    }
    __syncthreads();
  }
  // coalesced write of 32 x 64 out tile
#pragma unroll
  for (int t = 0; t < 2; t++) {
    int idx = tid + 256 * t;          // 0..511, 16 float4 per row
    int row = idx >> 4, f4 = idx & 15;
    float4 v = *(float4*)&rbuf[(size_t)row * 68 + f4 * 4];
    *(float4*)&g_oh[((size_t)bh * 1024 + i0 + row) * 64 + f4 * 4] = v;
  }
}

// ---------------- Kernel 3: pe_sum via mma (pe hi only, 2-pass) -------------
__global__ __launch_bounds__(256) void pes_mma(const float* __restrict__ pe) {
  __shared__ __nv_bfloat16 AH[32 * PSTRIDE], AL[32 * PSTRIDE];
  __shared__ __nv_bfloat16 PH[32 * PSTRIDE];

  int tid = threadIdx.x;
  int wid = tid >> 5, lane = tid & 31;
  int i = blockIdx.x;
  int mw = (wid & 1) * 16;        // bh rows
  int nw = (wid >> 1) * 8;        // c cols
  int r = lane >> 2, kq = (lane & 3) * 2;

  float acc[4] = {};
  for (int kc = 0; kc < 8; kc++) {
    if (kc) __syncthreads();
#pragma unroll
    for (int t = 0; t < 2; t++) {
      int idx = tid + 256 * t;
      int row = idx >> 4, seg = idx & 15;
      size_t gsrc = ((size_t)row << 20) + ((size_t)i << 10) + kc * 128 + seg * 8;
      int so = row * PSTRIDE + seg * 8;
      *(uint4*)(AH + so) = *(const uint4*)(g_attn_h + gsrc);
      *(uint4*)(AL + so) = *(const uint4*)(g_attn_l + gsrc);
    }
    // stage pe[i] chunk transposed (hi only): peT[c][j]
#pragma unroll
    for (int t = 0; t < 4; t++) {
      int idx = tid + 256 * t;
      int j = idx >> 3, c4 = idx & 7;
      float4 v = *(const float4*)(
          pe + (((size_t)i << 10) + kc * 128 + j) * 32 + c4 * 4);
      PH[(c4 * 4 + 0) * PSTRIDE + j] = __float2bfloat16_rn(v.x);
      PH[(c4 * 4 + 1) * PSTRIDE + j] = __float2bfloat16_rn(v.y);
      PH[(c4 * 4 + 2) * PSTRIDE + j] = __float2bfloat16_rn(v.z);
      PH[(c4 * 4 + 3) * PSTRIDE + j] = __float2bfloat16_rn(v.w);
    }
    __syncthreads();
#pragma unroll
    for (int kb = 0; kb < 8; kb++) {
      const __nv_bfloat16* p = AH + (mw + r) * PSTRIDE + kb * 16 + kq;
      uint32_t ah4[4] = {*(const uint32_t*)p,
                         *(const uint32_t*)(p + 8 * PSTRIDE),
                         *(const uint32_t*)(p + 8),
                         *(const uint32_t*)(p + 8 * PSTRIDE + 8)};
      const __nv_bfloat16* q = AL + (mw + r) * PSTRIDE + kb * 16 + kq;
      uint32_t al4[4] = {*(const uint32_t*)q,
                         *(const uint32_t*)(q + 8 * PSTRIDE),
                         *(const uint32_t*)(q + 8),
                         *(const uint32_t*)(q + 8 * PSTRIDE + 8)};
      const __nv_bfloat16* pb = PH + (nw + r) * PSTRIDE + kb * 16 + kq;
      uint32_t bh2[2] = {*(const uint32_t*)pb, *(const uint32_t*)(pb + 8)};
      mma16816(acc, ah4, bh2);
      mma16816(acc, al4, bh2);
    }
  }
  int c = nw + (lane & 3) * 2;
  int b0 = mw + r, b1 = b0 + 8;
  *(float2*)&g_pes[(((size_t)b0 << 10) + i) * 32 + c] = make_float2(acc[0], acc[1]);
  *(float2*)&g_pes[(((size_t)b1 << 10) + i) * 32 + c] = make_float2(acc[2], acc[3]);
}

// ---------------- Kernel 4: merged = out_head + pe_sum@Wpe + bpe (split) ----
__global__ __launch_bounds__(256) void merge_kernel(
    const float* __restrict__ Wpe, const float* __restrict__ bpe) {
  __shared__ float wpe_s[32 * 64];
  __shared__ float pes_s[32 * 32];
  __shared__ float bpe_s[64];
  int bh = blockIdx.x;
  int n0 = blockIdx.y * 32;
  int tid = threadIdx.x;
#pragma unroll
  for (int r = 0; r < 8; r++) wpe_s[tid + r * 256] = Wpe[tid + r * 256];
  if (tid < 64) bpe_s[tid] = bpe[tid];
  {
    int nl = tid >> 3, cc = tid & 7;
    *(float4*)&pes_s[nl * 32 + cc * 4] =
        *(const float4*)(g_pes + ((size_t)bh * 1024 + n0 + nl) * 32 + cc * 4);
  }
  __syncthreads();
  int nl = tid >> 3;
  int d0 = (tid & 7) * 8;
  int b = bh >> 3, h = bh & 7;
  const float* ohp = g_oh + ((size_t)bh * 1024 + n0 + nl) * 64 + d0;
  float o[8];
#pragma unroll
  for (int dd = 0; dd < 8; dd++) o[dd] = bpe_s[d0 + dd] + ohp[dd];
#pragma unroll 8
  for (int c = 0; c < 32; c++) {
    float pv = pes_s[nl * 32 + c];
#pragma unroll
    for (int dd = 0; dd < 8; dd++) o[dd] += pv * wpe_s[c * 64 + d0 + dd];
  }
  size_t mp = ((size_t)(b * 1024 + n0 + nl)) * 512 + h * 64 + d0;
  B16x8 hh, ll;
#pragma unroll
  for (int dd = 0; dd < 8; dd++) split2(o[dd], hh.h[dd], ll.h[dd]);
  *(uint4*)&g_mh[mp] = hh.u;
  *(uint4*)&g_ml[mp] = ll.u;
}

// ---------------- Kernel 5: out = merged @ Wproj via mma.sync ----------------
// M=4096, N=256, K=512. CTA 128m x 64n, grid (32, 4).
__global__ __launch_bounds__(256) void proj_mma(float* __restrict__ out) {
  extern __shared__ __nv_bfloat16 sm[];
  __nv_bfloat16* MH = sm;
  __nv_bfloat16* ML = MH + 128 * LDSTRIDE;
  __nv_bfloat16* WH = ML + 128 * LDSTRIDE;
  __nv_bfloat16* WL = WH + 64 * LDSTRIDE;

  int tid = threadIdx.x;
  int wid = tid >> 5, lane = tid & 31;
  int m0 = blockIdx.x * 128;
  int n0 = blockIdx.y * 64;

  int m_w = (wid >> 1) * 32, n_w = (wid & 1) * 32;
  int r = lane >> 2;
  int g = lane >> 3, rw = lane & 7;

  float c[2][4][4];
#pragma unroll
  for (int mt = 0; mt < 2; mt++)
#pragma unroll
    for (int nt = 0; nt < 4; nt++)
#pragma unroll
      for (int e = 0; e < 4; e++) c[mt][nt][e] = 0.f;

  for (int ck = 0; ck < 8; ck++) {
    if (ck) __syncthreads();
#pragma unroll
    for (int t = 0; t < 4; t++) {
      int idx = tid + 256 * t;
      int rr = idx >> 3, seg = idx & 7;
      int so = rr * LDSTRIDE + seg * 8;
      size_t gs = (size_t)(m0 + rr) * 512 + ck * 64 + seg * 8;
      *(uint4*)(MH + so) = *(const uint4*)(g_mh + gs);
      *(uint4*)(ML + so) = *(const uint4*)(g_ml + gs);
    }
#pragma unroll
    for (int t = 0; t < 2; t++) {
      int idx = tid + 256 * t;
      int d = idx >> 3, seg = idx & 7;
      int so = d * LDSTRIDE + seg * 8;
      size_t gs = (size_t)(n0 + d) * 512 + ck * 64 + seg * 8;
      *(uint4*)(WH + so) = *(const uint4*)(g_wpth + gs);
      *(uint4*)(WL + so) = *(const uint4*)(g_wptl + gs);
    }
    __syncthreads();
#pragma unroll
    for (int kb = 0; kb < 64; kb += 16) {
      uint32_t ah[2][4], al[2][4];
#pragma unroll
      for (int mt = 0; mt < 2; mt++) {
        ldsm4(ah[mt], MH + (m_w + mt * 16 + (g & 1) * 8 + rw) * LDSTRIDE + kb + (g >> 1) * 8);
        ldsm4(al[mt], ML + (m_w + mt * 16 + (g & 1) * 8 + rw) * LDSTRIDE + kb + (g >> 1) * 8);
      }
      uint32_t bh4[2][4], bl4[2][4];
#pragma unroll
      for (int p = 0; p < 2; p++) {
        ldsm4(bh4[p], WH + (n_w + p * 16 + (g >> 1) * 8 + rw) * LDSTRIDE + kb + (g & 1) * 8);
        ldsm4(bl4[p], WL + (n_w + p * 16 + (g >> 1) * 8 + rw) * LDSTRIDE + kb + (g & 1) * 8);
      }
#pragma unroll
      for (int mt = 0; mt < 2; mt++)
#pragma unroll
        for (int p = 0; p < 2; p++) {
          mma16816(c[mt][2 * p], ah[mt], bh4[p]);
          mma16816(c[mt][2 * p], ah[mt], bl4[p]);
          mma16816(c[mt][2 * p], al[mt], bh4[p]);
          mma16816(c[mt][2 * p + 1], ah[mt], bh4[p] + 2);
          mma16816(c[mt][2 * p + 1], ah[mt], bl4[p] + 2);
          mma16816(c[mt][2 * p + 1], al[mt], bh4[p] + 2);
        }
    }
  }

#pragma unroll
  for (int mt = 0; mt < 2; mt++) {
#pragma unroll
    for (int nt = 0; nt < 4; nt++) {
      int row = m0 + m_w + mt * 16 + r;
      int col = n0 + n_w + nt * 8 + (lane & 3) * 2;
      float* dst = out + (size_t)row * 256 + col;
      *(float2*)dst = make_float2(c[mt][nt][0], c[mt][nt][1]);
      *(float2*)(dst + 8 * 256) = make_float2(c[mt][nt][2], c[mt][nt][3]);
    }
  }
}

// ---------------- launch -----------------------------------------------------
extern "C" void kernel_launch(void* const* d_in, const int* in_sizes, int n_in,
                              void* d_out, int out_size) {
  const float* x     = (const float*)d_in[0];
  const float* pe    = (const float*)d_in[1];
  const float* Wq    = (const float*)d_in[2];
  const float* Wk    = (const float*)d_in[3];
  const float* Wv    = (const float*)d_in[4];
  const float* bv    = (const float*)d_in[5];
  const float* Wpe   = (const float*)d_in[6];
  const float* bpe   = (const float*)d_in[7];
  const float* Wproj = (const float*)d_in[8];
  float* out = (float*)d_out;

  cudaFuncSetAttribute(qkv_mma, cudaFuncAttributeMaxDynamicSharedMemorySize,
                       GEMM_SMEM_BYTES);
  cudaFuncSetAttribute(scoresm, cudaFuncAttributeMaxDynamicSharedMemorySize,
                       FSM_SMEM_BYTES);
  cudaFuncSetAttribute(proj_mma, cudaFuncAttributeMaxDynamicSharedMemorySize,
                       GEMM_SMEM_BYTES);

  split_x<<<1024, 256>>>(x);
  prep_w<<<512, 256>>>(Wq, Wk, Wv, Wproj);
  qkv_mma<<<dim3(32, 24), 256, GEMM_SMEM_BYTES>>>(bv);
  scoresm<<<dim3(32, 32), 256, FSM_SMEM_BYTES>>>();
  pes_mma<<<1024, 256>>>(pe);
  merge_kernel<<<dim3(32, 32), 256>>>(Wpe, bpe);
  proj_mma<<<dim3(32, 4), 256, GEMM_SMEM_BYTES>>>(out);
}

// round 11
// speedup vs baseline: 1.1450x; 1.1450x over previous
#include <cuda_runtime.h>
#include <cuda_bf16.h>
#include <cstdint>

#define NSEQ 1024
#define DIM  256
#define HEADS 8
#define EDIM 512
#define HD   64
#define PEC  32
#define BH   32           // B*HEADS
#define ROWS 4096         // B*N

// ---------------- scratch (device globals; no runtime allocation) ----------
__device__ __nv_bfloat16 g_xh[ROWS * DIM], g_xl[ROWS * DIM];
__device__ __nv_bfloat16 g_wth[1536 * 256], g_wtl[1536 * 256];   // [n][k]
__device__ __nv_bfloat16 g_wpth[256 * 512], g_wptl[256 * 512];   // [n][k]
__device__ __nv_bfloat16 g_qh[BH * NSEQ * HD];
__device__ __nv_bfloat16 g_ql[BH * NSEQ * HD];
__device__ __nv_bfloat16 g_kh[BH * NSEQ * HD];
__device__ __nv_bfloat16 g_kl[BH * NSEQ * HD];
__device__ __nv_bfloat16 g_vth[BH * HD * NSEQ];   // transposed: [bh][d][n]
__device__ __nv_bfloat16 g_vtl[BH * HD * NSEQ];
__device__ __nv_bfloat16 g_attn_h[(size_t)BH * NSEQ * NSEQ];  // 64 MB
__device__ __nv_bfloat16 g_attn_l[(size_t)BH * NSEQ * NSEQ];  // 64 MB
__device__ float g_oh[BH * NSEQ * HD];
__device__ float g_pes[BH * NSEQ * PEC];
__device__ __nv_bfloat16 g_mh[ROWS * EDIM], g_ml[ROWS * EDIM];

union B16x8 { __nv_bfloat16 h[8]; uint4 u; };
union B16x4 { __nv_bfloat16 h[4]; uint2 u; };
union B16x2 { __nv_bfloat16 h[2]; uint32_t u; };

__device__ __forceinline__ void split2(float x, __nv_bfloat16& h, __nv_bfloat16& l) {
  h = __float2bfloat16_rn(x);
  l = __float2bfloat16_rn(x - __bfloat162float(h));
}

// m16n8k16 bf16 mma with fp32 accumulate (row.col)
__device__ __forceinline__ void mma16816(float* c, const uint32_t* a,
                                         const uint32_t* b) {
  asm volatile(
      "mma.sync.aligned.m16n8k16.row.col.f32.bf16.bf16.f32 "
      "{%0,%1,%2,%3}, {%4,%5,%6,%7}, {%8,%9}, {%0,%1,%2,%3};"
      : "+f"(c[0]), "+f"(c[1]), "+f"(c[2]), "+f"(c[3])
      : "r"(a[0]), "r"(a[1]), "r"(a[2]), "r"(a[3]), "r"(b[0]), "r"(b[1]));
}

// ldmatrix x4: 4 8x8 b16 tiles; lane group g=lane>>3 supplies address of tile g
__device__ __forceinline__ void ldsm4(uint32_t* d, const __nv_bfloat16* p) {
  uint32_t a = (uint32_t)__cvta_generic_to_shared(p);
  asm volatile("ldmatrix.sync.aligned.m8n8.x4.shared.b16 {%0,%1,%2,%3}, [%4];"
               : "=r"(d[0]), "=r"(d[1]), "=r"(d[2]), "=r"(d[3]) : "r"(a));
}

// 16B async copy gmem -> smem
__device__ __forceinline__ void cp16(__nv_bfloat16* smem_ptr, const __nv_bfloat16* gptr) {
  uint32_t s = (uint32_t)__cvta_generic_to_shared(smem_ptr);
  asm volatile("cp.async.cg.shared.global [%0], [%1], 16;" :: "r"(s), "l"(gptr));
}
#define CP_COMMIT() asm volatile("cp.async.commit_group;" ::: "memory")
#define CP_WAIT1()  asm volatile("cp.async.wait_group 1;" ::: "memory")
#define CP_WAIT0()  asm volatile("cp.async.wait_group 0;" ::: "memory")

#define LDSTRIDE 72   // bf16 units per SMEM row (64 data + 8 pad)
#define PSTRIDE 136   // bf16 units per SMEM row (128 data + 8 pad)
#define GEMM_SMEM_BYTES ((2 * 128 + 2 * 64) * LDSTRIDE * 2)   // 55296

// ---------------- prep: split x into bf16 hi/lo ------------------------------
__global__ __launch_bounds__(256) void split_x(const float* __restrict__ x) {
  int idx = (blockIdx.x * 256 + threadIdx.x) * 4;
  float4 v = *(const float4*)(x + idx);
  B16x4 hh, ll;
  split2(v.x, hh.h[0], ll.h[0]); split2(v.y, hh.h[1], ll.h[1]);
  split2(v.z, hh.h[2], ll.h[2]); split2(v.w, hh.h[3], ll.h[3]);
  *(uint2*)&g_xh[idx] = hh.u;
  *(uint2*)&g_xl[idx] = ll.u;
}

// ---------------- prep: transpose + split weights -----------------------------
__global__ __launch_bounds__(256) void prep_w(
    const float* __restrict__ Wq, const float* __restrict__ Wk,
    const float* __restrict__ Wv, const float* __restrict__ Wproj) {
  int id = blockIdx.x * 256 + threadIdx.x;
  if (id < 98304) {                 // WT: 1536 n x 64 k-groups
    int n = id >> 6, k0 = (id & 63) * 4;
    int sel = n >> 9, col = n & 511;
    const float* W = (sel == 0) ? Wq : (sel == 1) ? Wk : Wv;
#pragma unroll
    for (int q = 0; q < 4; q++) {
      float v = W[(k0 + q) * 512 + col];
      split2(v, g_wth[n * 256 + k0 + q], g_wtl[n * 256 + k0 + q]);
    }
  } else {                          // WprojT: 256 n x 128 k-groups
    int id2 = id - 98304;
    int n = id2 >> 7, k0 = (id2 & 127) * 4;
#pragma unroll
    for (int q = 0; q < 4; q++) {
      float v = Wproj[(k0 + q) * 256 + n];
      split2(v, g_wpth[n * 512 + k0 + q], g_wptl[n * 512 + k0 + q]);
    }
  }
}

// ---------------- Kernel 1: QKV projection via mma.sync ---------------------
// M=4096, N=1536, K=256. CTA 128m x 64n, grid (32, 24). 8 warps: 4m x 2n.
__global__ __launch_bounds__(256) void qkv_mma(const float* __restrict__ bv) {
  extern __shared__ __nv_bfloat16 sm[];
  __nv_bfloat16* XH = sm;
  __nv_bfloat16* XL = XH + 128 * LDSTRIDE;
  __nv_bfloat16* WH = XL + 128 * LDSTRIDE;
  __nv_bfloat16* WL = WH + 64 * LDSTRIDE;

  int tid = threadIdx.x;
  int wid = tid >> 5, lane = tid & 31;
  int m0 = blockIdx.x * 128;
  int n0 = blockIdx.y * 64;
  int sel = n0 / 512;
  int e0 = n0 % 512;
  int h = e0 / 64;

  int m_w = (wid >> 1) * 32, n_w = (wid & 1) * 32;
  int r = lane >> 2;
  int g = lane >> 3, rw = lane & 7;

  float c[2][4][4];
#pragma unroll
  for (int mt = 0; mt < 2; mt++)
#pragma unroll
    for (int nt = 0; nt < 4; nt++)
#pragma unroll
      for (int e = 0; e < 4; e++) c[mt][nt][e] = 0.f;

  for (int ck = 0; ck < 4; ck++) {
    if (ck) __syncthreads();
#pragma unroll
    for (int t = 0; t < 4; t++) {
      int idx = tid + 256 * t;
      int rr = idx >> 3, seg = idx & 7;
      int so = rr * LDSTRIDE + seg * 8;
      size_t gs = (size_t)(m0 + rr) * 256 + ck * 64 + seg * 8;
      *(uint4*)(XH + so) = *(const uint4*)(g_xh + gs);
      *(uint4*)(XL + so) = *(const uint4*)(g_xl + gs);
    }
#pragma unroll
    for (int t = 0; t < 2; t++) {
      int idx = tid + 256 * t;
      int d = idx >> 3, seg = idx & 7;
      int so = d * LDSTRIDE + seg * 8;
      size_t gs = (size_t)(n0 + d) * 256 + ck * 64 + seg * 8;
      *(uint4*)(WH + so) = *(const uint4*)(g_wth + gs);
      *(uint4*)(WL + so) = *(const uint4*)(g_wtl + gs);
    }
    __syncthreads();
#pragma unroll
    for (int kb = 0; kb < 64; kb += 16) {
      uint32_t ah[2][4], al[2][4];
#pragma unroll
      for (int mt = 0; mt < 2; mt++) {
        ldsm4(ah[mt], XH + (m_w + mt * 16 + (g & 1) * 8 + rw) * LDSTRIDE + kb + (g >> 1) * 8);
        ldsm4(al[mt], XL + (m_w + mt * 16 + (g & 1) * 8 + rw) * LDSTRIDE + kb + (g >> 1) * 8);
      }
      uint32_t bh4[2][4], bl4[2][4];
#pragma unroll
      for (int p = 0; p < 2; p++) {
        ldsm4(bh4[p], WH + (n_w + p * 16 + (g >> 1) * 8 + rw) * LDSTRIDE + kb + (g & 1) * 8);
        ldsm4(bl4[p], WL + (n_w + p * 16 + (g >> 1) * 8 + rw) * LDSTRIDE + kb + (g & 1) * 8);
      }
#pragma unroll
      for (int mt = 0; mt < 2; mt++)
#pragma unroll
        for (int p = 0; p < 2; p++) {
          mma16816(c[mt][2 * p], ah[mt], bh4[p]);
          mma16816(c[mt][2 * p], ah[mt], bl4[p]);
          mma16816(c[mt][2 * p], al[mt], bh4[p]);
          mma16816(c[mt][2 * p + 1], ah[mt], bh4[p] + 2);
          mma16816(c[mt][2 * p + 1], ah[mt], bl4[p] + 2);
          mma16816(c[mt][2 * p + 1], al[mt], bh4[p] + 2);
        }
    }
  }

#pragma unroll
  for (int mt = 0; mt < 2; mt++) {
#pragma unroll
    for (int nt = 0; nt < 4; nt++) {
      int colw = n_w + nt * 8 + (lane & 3) * 2;   // 0..62, even
      int d = colw;                                // channel within head
      int e = e0 + colw;
#pragma unroll
      for (int half = 0; half < 2; half++) {
        int row = m0 + m_w + mt * 16 + r + half * 8;
        float v0 = c[mt][nt][half * 2 + 0];
        float v1 = c[mt][nt][half * 2 + 1];
        int b = row >> 10, n = row & 1023;
        int bh = b * 8 + h;
        if (sel == 0) {
          v0 *= 0.125f; v1 *= 0.125f;
          B16x2 hp, lp;
          split2(v0, hp.h[0], lp.h[0]); split2(v1, hp.h[1], lp.h[1]);
          size_t idx = ((size_t)bh * 1024 + n) * 64 + d;
          *(uint32_t*)&g_qh[idx] = hp.u;
          *(uint32_t*)&g_ql[idx] = lp.u;
        } else if (sel == 1) {
          B16x2 hp, lp;
          split2(v0, hp.h[0], lp.h[0]); split2(v1, hp.h[1], lp.h[1]);
          size_t idx = ((size_t)bh * 1024 + n) * 64 + d;
          *(uint32_t*)&g_kh[idx] = hp.u;
          *(uint32_t*)&g_kl[idx] = lp.u;
        } else {
          v0 += bv[e]; v1 += bv[e + 1];
          __nv_bfloat16 hh, ll;
          split2(v0, hh, ll);
          size_t i0v = ((size_t)bh * 64 + d) * 1024 + n;
          g_vth[i0v] = hh; g_vtl[i0v] = ll;
          split2(v1, hh, ll);
          size_t i1v = ((size_t)bh * 64 + d + 1) * 1024 + n;
          g_vth[i1v] = hh; g_vtl[i1v] = ll;
        }
      }
    }
  }
}

// ---------------- Kernel 2: fused scores + softmax (16-row CTAs) ------------
// 2-pass split (q hi+lo vs k hi), cp.async double-buffered K, ldmatrix.
// CTA = 16 query rows x FULL 1024 cols. grid (64, 32). 8 warps, 16 cols each.
// Small CTA (<=128 regs, ~41.5 KB smem) => 2 CTAs/SM, independent barriers.
#define KSTAGE (128 * LDSTRIDE)     // 9216 elements per K stage
#define SM_SMEM_BYTES ((2 * 16 * LDSTRIDE + 2 * KSTAGE) * 2)   // 41472 B
__global__ __launch_bounds__(256, 2) void scoresm() {
  extern __shared__ __nv_bfloat16 smd[];
  __nv_bfloat16* QH = smd;
  __nv_bfloat16* QL = QH + 16 * LDSTRIDE;
  __nv_bfloat16* KHb = QL + 16 * LDSTRIDE;   // 2 stages of KSTAGE
  __shared__ float red[16][8];

  int tid = threadIdx.x;
  int wid = tid >> 5, lane = tid & 31;
  int bh = blockIdx.y;
  int i0 = blockIdx.x * 16;

  const __nv_bfloat16* qh = g_qh + (size_t)bh * NSEQ * HD;
  const __nv_bfloat16* ql = g_ql + (size_t)bh * NSEQ * HD;
  const __nv_bfloat16* kh = g_kh + (size_t)bh * NSEQ * HD;

  // stage q (16 x 64, hi/lo): threads 0..127, one uint4 per array
  if (tid < 128) {
    int r = tid >> 3, seg = tid & 7;
    int so = r * LDSTRIDE + seg * 8;
    *(uint4*)(QH + so) = *(const uint4*)(qh + (i0 + r) * 64 + seg * 8);
    *(uint4*)(QL + so) = *(const uint4*)(ql + (i0 + r) * 64 + seg * 8);
  }
  // prefetch K chunk 0 into stage 0 (hi only)
#pragma unroll
  for (int t = 0; t < 4; t++) {
    int idx = tid + 256 * t;
    int rr = idx >> 3, seg = idx & 7;
    cp16(KHb + rr * LDSTRIDE + seg * 8, kh + rr * 64 + seg * 8);
  }
  CP_COMMIT();

  int nwb = wid * 16;               // each warp owns 16 cols per 128-chunk
  int r = lane >> 2;
  int g = lane >> 3, rw = lane & 7;

  uint32_t ah[4][4], al[4][4];
  float acc[8][2][4];
#pragma unroll
  for (int jc = 0; jc < 8; jc++)
#pragma unroll
    for (int nt = 0; nt < 2; nt++)
#pragma unroll
      for (int e = 0; e < 4; e++) acc[jc][nt][e] = 0.f;

#pragma unroll
  for (int jc = 0; jc < 8; jc++) {
    int st = jc & 1;
    if (jc < 7) {
      int sn = st ^ 1;
#pragma unroll
      for (int t = 0; t < 4; t++) {
        int idx = tid + 256 * t;
        int rr = idx >> 3, seg = idx & 7;
        cp16(KHb + sn * KSTAGE + rr * LDSTRIDE + seg * 8,
             kh + ((jc + 1) * 128 + rr) * 64 + seg * 8);
      }
      CP_COMMIT();
      CP_WAIT1();
    } else {
      CP_WAIT0();
    }
    __syncthreads();
    const __nv_bfloat16* KH = KHb + st * KSTAGE;
    if (jc == 0) {
      // hoist q frags (hi and lo) for all 4 k-steps via ldmatrix
#pragma unroll
      for (int kb = 0; kb < 4; kb++) {
        ldsm4(ah[kb], QH + ((g & 1) * 8 + rw) * LDSTRIDE + kb * 16 + (g >> 1) * 8);
        ldsm4(al[kb], QL + ((g & 1) * 8 + rw) * LDSTRIDE + kb * 16 + (g >> 1) * 8);
      }
    }
#pragma unroll
    for (int kb = 0; kb < 4; kb++) {
      uint32_t b4[4];
      ldsm4(b4, KH + (nwb + (g >> 1) * 8 + rw) * LDSTRIDE + kb * 16 + (g & 1) * 8);
      mma16816(acc[jc][0], ah[kb], b4);
      mma16816(acc[jc][0], al[kb], b4);
      mma16816(acc[jc][1], ah[kb], b4 + 2);
      mma16816(acc[jc][1], al[kb], b4 + 2);
    }
    __syncthreads();   // all warps done reading stage st before refill
  }

  // ---- row softmax across the full 1024 columns ----
  int r0 = r, r1 = r0 + 8;
  float m0 = -1e30f, m1 = -1e30f;
#pragma unroll
  for (int jc = 0; jc < 8; jc++)
#pragma unroll
    for (int nt = 0; nt < 2; nt++) {
      m0 = fmaxf(m0, fmaxf(acc[jc][nt][0], acc[jc][nt][1]));
      m1 = fmaxf(m1, fmaxf(acc[jc][nt][2], acc[jc][nt][3]));
    }
#pragma unroll
  for (int o = 1; o <= 2; o <<= 1) {
    m0 = fmaxf(m0, __shfl_xor_sync(~0u, m0, o));
    m1 = fmaxf(m1, __shfl_xor_sync(~0u, m1, o));
  }
  if ((lane & 3) == 0) { red[r0][wid] = m0; red[r1][wid] = m1; }
  __syncthreads();
#pragma unroll
  for (int q = 0; q < 8; q++) {
    m0 = fmaxf(m0, red[r0][q]);
    m1 = fmaxf(m1, red[r1][q]);
  }
  __syncthreads();

  float s0 = 0.f, s1 = 0.f;
#pragma unroll
  for (int jc = 0; jc < 8; jc++)
#pragma unroll
    for (int nt = 0; nt < 2; nt++) {
      acc[jc][nt][0] = __expf(acc[jc][nt][0] - m0);
      acc[jc][nt][1] = __expf(acc[jc][nt][1] - m0);
      acc[jc][nt][2] = __expf(acc[jc][nt][2] - m1);
      acc[jc][nt][3] = __expf(acc[jc][nt][3] - m1);
      s0 += acc[jc][nt][0] + acc[jc][nt][1];
      s1 += acc[jc][nt][2] + acc[jc][nt][3];
    }
#pragma unroll
  for (int o = 1; o <= 2; o <<= 1) {
    s0 += __shfl_xor_sync(~0u, s0, o);
    s1 += __shfl_xor_sync(~0u, s1, o);
  }
  if ((lane & 3) == 0) { red[r0][wid] = s0; red[r1][wid] = s1; }
  __syncthreads();
  s0 = 0.f; s1 = 0.f;
#pragma unroll
  for (int q = 0; q < 8; q++) { s0 += red[r0][q]; s1 += red[r1][q]; }
  float inv0 = 1.f / s0, inv1 = 1.f / s1;

  size_t base0 = (((size_t)bh << 10) + (i0 + r0)) << 10;
  size_t base1 = (((size_t)bh << 10) + (i0 + r1)) << 10;
#pragma unroll
  for (int jc = 0; jc < 8; jc++) {
#pragma unroll
    for (int nt = 0; nt < 2; nt++) {
      int col = jc * 128 + nwb + nt * 8 + (lane & 3) * 2;
      float e0 = acc[jc][nt][0] * inv0, e1 = acc[jc][nt][1] * inv0;
      float e2 = acc[jc][nt][2] * inv1, e3 = acc[jc][nt][3] * inv1;
      B16x2 hp, lp;
      split2(e0, hp.h[0], lp.h[0]); split2(e1, hp.h[1], lp.h[1]);
      *(uint32_t*)(g_attn_h + base0 + col) = hp.u;
      *(uint32_t*)(g_attn_l + base0 + col) = lp.u;
      split2(e2, hp.h[0], lp.h[0]); split2(e3, hp.h[1], lp.h[1]);
      *(uint32_t*)(g_attn_h + base1 + col) = hp.u;
      *(uint32_t*)(g_attn_l + base1 + col) = lp.u;
    }
  }
}

// ---------------- Kernel 3: out_head = attn @ v (cp.async + ldmatrix) -------
#define AV_A (128 * LDSTRIDE)   // 9216
#define AV_V (64 * LDSTRIDE)    // 4608
#define AV_STAGE (2 * AV_A + 2 * AV_V)   // 27648 elements per stage
#define AV_SMEM_BYTES (2 * AV_STAGE * 2) // 110592 B
__global__ __launch_bounds__(256) void av_mma() {
  extern __shared__ __nv_bfloat16 smd[];

  int tid = threadIdx.x;
  int wid = tid >> 5, lane = tid & 31;
  int bh = blockIdx.y;
  int i0 = blockIdx.x * 128;

  const __nv_bfloat16* vth = g_vth + (size_t)bh * HD * NSEQ;
  const __nv_bfloat16* vtl = g_vtl + (size_t)bh * HD * NSEQ;

  int m_w = (wid >> 1) * 32;
  int n_w = (wid & 1) * 32;
  int r = lane >> 2;
  int g = lane >> 3, rw = lane & 7;

  float c[2][4][4];
#pragma unroll
  for (int mt = 0; mt < 2; mt++)
#pragma unroll
    for (int nt = 0; nt < 4; nt++)
#pragma unroll
      for (int e = 0; e < 4; e++) c[mt][nt][e] = 0.f;

  // prefetch chunk 0 into stage 0
#pragma unroll
  for (int t = 0; t < 4; t++) {
    int idx = tid + 256 * t;
    int rr = idx >> 3, seg = idx & 7;
    size_t gsrc = ((((size_t)bh << 10) + i0 + rr) << 10) + seg * 8;
    int so = rr * LDSTRIDE + seg * 8;
    cp16(smd + so, g_attn_h + gsrc);
    cp16(smd + AV_A + so, g_attn_l + gsrc);
  }
#pragma unroll
  for (int t = 0; t < 2; t++) {
    int idx = tid + 256 * t;
    int d = idx >> 3, seg = idx & 7;
    int so = 2 * AV_A + d * LDSTRIDE + seg * 8;
    cp16(smd + so, vth + (size_t)d * 1024 + seg * 8);
    cp16(smd + AV_V + so, vtl + (size_t)d * 1024 + seg * 8);
  }
  CP_COMMIT();

  for (int ck = 0; ck < 16; ck++) {
    int st = ck & 1;
    if (ck < 15) {
      int sn = st ^ 1;
      __nv_bfloat16* base = smd + sn * AV_STAGE;
#pragma unroll
      for (int t = 0; t < 4; t++) {
        int idx = tid + 256 * t;
        int rr = idx >> 3, seg = idx & 7;
        size_t gsrc = ((((size_t)bh << 10) + i0 + rr) << 10) + (ck + 1) * 64 + seg * 8;
        int so = rr * LDSTRIDE + seg * 8;
        cp16(base + so, g_attn_h + gsrc);
        cp16(base + AV_A + so, g_attn_l + gsrc);
      }
#pragma unroll
      for (int t = 0; t < 2; t++) {
        int idx = tid + 256 * t;
        int d = idx >> 3, seg = idx & 7;
        int so = 2 * AV_A + d * LDSTRIDE + seg * 8;
        cp16(base + so, vth + (size_t)d * 1024 + (ck + 1) * 64 + seg * 8);
        cp16(base + AV_V + so, vtl + (size_t)d * 1024 + (ck + 1) * 64 + seg * 8);
      }
      CP_COMMIT();
      CP_WAIT1();
    } else {
      CP_WAIT0();
    }
    __syncthreads();
    const __nv_bfloat16* AHs = smd + st * AV_STAGE;
    const __nv_bfloat16* ALs = AHs + AV_A;
    const __nv_bfloat16* VHs = ALs + AV_A;
    const __nv_bfloat16* VLs = VHs + AV_V;

#pragma unroll
    for (int kb = 0; kb < 64; kb += 16) {
      uint32_t ah[2][4], al[2][4];
#pragma unroll
      for (int mt = 0; mt < 2; mt++) {
        ldsm4(ah[mt], AHs + (m_w + mt * 16 + (g & 1) * 8 + rw) * LDSTRIDE + kb + (g >> 1) * 8);
        ldsm4(al[mt], ALs + (m_w + mt * 16 + (g & 1) * 8 + rw) * LDSTRIDE + kb + (g >> 1) * 8);
      }
      uint32_t bh4[2][4], bl4[2][4];
#pragma unroll
      for (int p = 0; p < 2; p++) {
        ldsm4(bh4[p], VHs + (n_w + p * 16 + (g >> 1) * 8 + rw) * LDSTRIDE + kb + (g & 1) * 8);
        ldsm4(bl4[p], VLs + (n_w + p * 16 + (g >> 1) * 8 + rw) * LDSTRIDE + kb + (g & 1) * 8);
      }
#pragma unroll
      for (int mt = 0; mt < 2; mt++)
#pragma unroll
        for (int p = 0; p < 2; p++) {
          mma16816(c[mt][2 * p], ah[mt], bh4[p]);
          mma16816(c[mt][2 * p], ah[mt], bl4[p]);
          mma16816(c[mt][2 * p], al[mt], bh4[p]);
          mma16816(c[mt][2 * p + 1], ah[mt], bh4[p] + 2);
          mma16816(c[mt][2 * p + 1], ah[mt], bl4[p] + 2);
          mma16816(c[mt][2 * p + 1], al[mt], bh4[p] + 2);
        }
    }
    __syncthreads();
  }

#pragma unroll
  for (int mt = 0; mt < 2; mt++) {
#pragma unroll
    for (int nt = 0; nt < 4; nt++) {
      int row = i0 + m_w + mt * 16 + r;
      int col = n_w + nt * 8 + (lane & 3) * 2;
      float* dst = g_oh + ((size_t)bh * 1024 + row) * 64 + col;
      *(float2*)dst = make_float2(c[mt][nt][0], c[mt][nt][1]);
      *(float2*)(dst + 8 * 64) = make_float2(c[mt][nt][2], c[mt][nt][3]);
    }
  }
}

// ---------------- Kernel 4: pe_sum via mma (attn hi x pe hi, 1-pass) --------
__global__ __launch_bounds__(256) void pes_mma(const float* __restrict__ pe) {
  __shared__ __nv_bfloat16 AH[32 * PSTRIDE];
  __shared__ __nv_bfloat16 PH[32 * PSTRIDE];

  int tid = threadIdx.x;
  int wid = tid >> 5, lane = tid & 31;
  int i = blockIdx.x;
  int mw = (wid & 1) * 16;        // bh rows
  int nw = (wid >> 1) * 8;        // c cols
  int r = lane >> 2, kq = (lane & 3) * 2;

  float acc[4] = {};
  for (int kc = 0; kc < 8; kc++) {
    if (kc) __syncthreads();
#pragma unroll
    for (int t = 0; t < 2; t++) {
      int idx = tid + 256 * t;
      int row = idx >> 4, seg = idx & 15;
      size_t gsrc = ((size_t)row << 20) + ((size_t)i << 10) + kc * 128 + seg * 8;
      int so = row * PSTRIDE + seg * 8;
      *(uint4*)(AH + so) = *(const uint4*)(g_attn_h + gsrc);
    }
    // stage pe[i] chunk transposed (hi only): peT[c][j]
#pragma unroll
    for (int t = 0; t < 4; t++) {
      int idx = tid + 256 * t;
      int j = idx >> 3, c4 = idx & 7;
      float4 v = *(const float4*)(
          pe + (((size_t)i << 10) + kc * 128 + j) * 32 + c4 * 4);
      PH[(c4 * 4 + 0) * PSTRIDE + j] = __float2bfloat16_rn(v.x);
      PH[(c4 * 4 + 1) * PSTRIDE + j] = __float2bfloat16_rn(v.y);
      PH[(c4 * 4 + 2) * PSTRIDE + j] = __float2bfloat16_rn(v.z);
      PH[(c4 * 4 + 3) * PSTRIDE + j] = __float2bfloat16_rn(v.w);
    }
    __syncthreads();
#pragma unroll
    for (int kb = 0; kb < 8; kb++) {
      const __nv_bfloat16* p = AH + (mw + r) * PSTRIDE + kb * 16 + kq;
      uint32_t ah4[4] = {*(const uint32_t*)p,
                         *(const uint32_t*)(p + 8 * PSTRIDE),
                         *(const uint32_t*)(p + 8),
                         *(const uint32_t*)(p + 8 * PSTRIDE + 8)};
      const __nv_bfloat16* pb = PH + (nw + r) * PSTRIDE + kb * 16 + kq;
      uint32_t bh2[2] = {*(const uint32_t*)pb, *(const uint32_t*)(pb + 8)};
      mma16816(acc, ah4, bh2);
    }
  }
  int c = nw + (lane & 3) * 2;
  int b0 = mw + r, b1 = b0 + 8;
  *(float2*)&g_pes[(((size_t)b0 << 10) + i) * 32 + c] = make_float2(acc[0], acc[1]);
  *(float2*)&g_pes[(((size_t)b1 << 10) + i) * 32 + c] = make_float2(acc[2], acc[3]);
}

// ---------------- Kernel 5: merged = out_head + pe_sum@Wpe + bpe (split) ----
__global__ __launch_bounds__(256) void merge_kernel(
    const float* __restrict__ Wpe, const float* __restrict__ bpe) {
  __shared__ float wpe_s[32 * 64];
  __shared__ float pes_s[32 * 32];
  __shared__ float bpe_s[64];
  int bh = blockIdx.x;
  int n0 = blockIdx.y * 32;
  int tid = threadIdx.x;
#pragma unroll
  for (int r = 0; r < 8; r++) wpe_s[tid + r * 256] = Wpe[tid + r * 256];
  if (tid < 64) bpe_s[tid] = bpe[tid];
  {
    int nl = tid >> 3, cc = tid & 7;
    *(float4*)&pes_s[nl * 32 + cc * 4] =
        *(const float4*)(g_pes + ((size_t)bh * 1024 + n0 + nl) * 32 + cc * 4);
  }
  __syncthreads();
  int nl = tid >> 3;
  int d0 = (tid & 7) * 8;
  int b = bh >> 3, h = bh & 7;
  const float* ohp = g_oh + ((size_t)bh * 1024 + n0 + nl) * 64 + d0;
  float o[8];
#pragma unroll
  for (int dd = 0; dd < 8; dd++) o[dd] = bpe_s[d0 + dd] + ohp[dd];
#pragma unroll 8
  for (int c = 0; c < 32; c++) {
    float pv = pes_s[nl * 32 + c];
#pragma unroll
    for (int dd = 0; dd < 8; dd++) o[dd] += pv * wpe_s[c * 64 + d0 + dd];
  }
  size_t mp = ((size_t)(b * 1024 + n0 + nl)) * 512 + h * 64 + d0;
  B16x8 hh, ll;
#pragma unroll
  for (int dd = 0; dd < 8; dd++) split2(o[dd], hh.h[dd], ll.h[dd]);
  *(uint4*)&g_mh[mp] = hh.u;
  *(uint4*)&g_ml[mp] = ll.u;
}

// ---------------- Kernel 6: out = merged @ Wproj via mma.sync ----------------
// M=4096, N=256, K=512. CTA 128m x 64n, grid (32, 4).
__global__ __launch_bounds__(256) void proj_mma(float* __restrict__ out) {
  extern __shared__ __nv_bfloat16 sm[];
  __nv_bfloat16* MH = sm;
  __nv_bfloat16* ML = MH + 128 * LDSTRIDE;
  __nv_bfloat16* WH = ML + 128 * LDSTRIDE;
  __nv_bfloat16* WL = WH + 64 * LDSTRIDE;

  int tid = threadIdx.x;
  int wid = tid >> 5, lane = tid & 31;
  int m0 = blockIdx.x * 128;
  int n0 = blockIdx.y * 64;

  int m_w = (wid >> 1) * 32, n_w = (wid & 1) * 32;
  int r = lane >> 2;
  int g = lane >> 3, rw = lane & 7;

  float c[2][4][4];
#pragma unroll
  for (int mt = 0; mt < 2; mt++)
#pragma unroll
    for (int nt = 0; nt < 4; nt++)
#pragma unroll
      for (int e = 0; e < 4; e++) c[mt][nt][e] = 0.f;

  for (int ck = 0; ck < 8; ck++) {
    if (ck) __syncthreads();
#pragma unroll
    for (int t = 0; t < 4; t++) {
      int idx = tid + 256 * t;
      int rr = idx >> 3, seg = idx & 7;
      int so = rr * LDSTRIDE + seg * 8;
      size_t gs = (size_t)(m0 + rr) * 512 + ck * 64 + seg * 8;
      *(uint4*)(MH + so) = *(const uint4*)(g_mh + gs);
      *(uint4*)(ML + so) = *(const uint4*)(g_ml + gs);
    }
#pragma unroll
    for (int t = 0; t < 2; t++) {
      int idx = tid + 256 * t;
      int d = idx >> 3, seg = idx & 7;
      int so = d * LDSTRIDE + seg * 8;
      size_t gs = (size_t)(n0 + d) * 512 + ck * 64 + seg * 8;
      *(uint4*)(WH + so) = *(const uint4*)(g_wpth + gs);
      *(uint4*)(WL + so) = *(const uint4*)(g_wptl + gs);
    }
    __syncthreads();
#pragma unroll
    for (int kb = 0; kb < 64; kb += 16) {
      uint32_t ah[2][4], al[2][4];
#pragma unroll
      for (int mt = 0; mt < 2; mt++) {
        ldsm4(ah[mt], MH + (m_w + mt * 16 + (g & 1) * 8 + rw) * LDSTRIDE + kb + (g >> 1) * 8);
        ldsm4(al[mt], ML + (m_w + mt * 16 + (g & 1) * 8 + rw) * LDSTRIDE + kb + (g >> 1) * 8);
      }
      uint32_t bh4[2][4], bl4[2][4];
#pragma unroll
      for (int p = 0; p < 2; p++) {
        ldsm4(bh4[p], WH + (n_w + p * 16 + (g >> 1) * 8 + rw) * LDSTRIDE + kb + (g & 1) * 8);
        ldsm4(bl4[p], WL + (n_w + p * 16 + (g >> 1) * 8 + rw) * LDSTRIDE + kb + (g & 1) * 8);
      }
#pragma unroll
      for (int mt = 0; mt < 2; mt++)
#pragma unroll
        for (int p = 0; p < 2; p++) {
          mma16816(c[mt][2 * p], ah[mt], bh4[p]);
          mma16816(c[mt][2 * p], ah[mt], bl4[p]);
          mma16816(c[mt][2 * p], al[mt], bh4[p]);
          mma16816(c[mt][2 * p + 1], ah[mt], bh4[p] + 2);
          mma16816(c[mt][2 * p + 1], ah[mt], bl4[p] + 2);
          mma16816(c[mt][2 * p + 1], al[mt], bh4[p] + 2);
        }
    }
  }

#pragma unroll
  for (int mt = 0; mt < 2; mt++) {
#pragma unroll
    for (int nt = 0; nt < 4; nt++) {
      int row = m0 + m_w + mt * 16 + r;
      int col = n0 + n_w + nt * 8 + (lane & 3) * 2;
      float* dst = out + (size_t)row * 256 + col;
      *(float2*)dst = make_float2(c[mt][nt][0], c[mt][nt][1]);
      *(float2*)(dst + 8 * 256) = make_float2(c[mt][nt][2], c[mt][nt][3]);
    }
  }
}

// ---------------- launch -----------------------------------------------------
extern "C" void kernel_launch(void* const* d_in, const int* in_sizes, int n_in,
                              void* d_out, int out_size) {
  const float* x     = (const float*)d_in[0];
  const float* pe    = (const float*)d_in[1];
  const float* Wq    = (const float*)d_in[2];
  const float* Wk    = (const float*)d_in[3];
  const float* Wv    = (const float*)d_in[4];
  const float* bv    = (const float*)d_in[5];
  const float* Wpe   = (const float*)d_in[6];
  const float* bpe   = (const float*)d_in[7];
  const float* Wproj = (const float*)d_in[8];
  float* out = (float*)d_out;

  cudaFuncSetAttribute(qkv_mma, cudaFuncAttributeMaxDynamicSharedMemorySize,
                       GEMM_SMEM_BYTES);
  cudaFuncSetAttribute(scoresm, cudaFuncAttributeMaxDynamicSharedMemorySize,
                       SM_SMEM_BYTES);
  cudaFuncSetAttribute(av_mma, cudaFuncAttributeMaxDynamicSharedMemorySize,
                       AV_SMEM_BYTES);
  cudaFuncSetAttribute(proj_mma, cudaFuncAttributeMaxDynamicSharedMemorySize,
                       GEMM_SMEM_BYTES);

  split_x<<<1024, 256>>>(x);
  prep_w<<<512, 256>>>(Wq, Wk, Wv, Wproj);
  qkv_mma<<<dim3(32, 24), 256, GEMM_SMEM_BYTES>>>(bv);
  scoresm<<<dim3(64, 32), 256, SM_SMEM_BYTES>>>();
  av_mma<<<dim3(8, 32), 256, AV_SMEM_BYTES>>>();
  pes_mma<<<1024, 256>>>(pe);
  merge_kernel<<<dim3(32, 32), 256>>>(Wpe, bpe);
  proj_mma<<<dim3(32, 4), 256, GEMM_SMEM_BYTES>>>(out);
}

// round 12
// speedup vs baseline: 1.3188x; 1.1518x over previous
#include <cuda_runtime.h>
#include <cuda_bf16.h>
#include <cstdint>

#define NSEQ 1024
#define DIM  256
#define HEADS 8
#define EDIM 512
#define HD   64
#define PEC  32
#define BH   32           // B*HEADS
#define ROWS 4096         // B*N

// ---------------- scratch (device globals; no runtime allocation) ----------
__device__ __nv_bfloat16 g_xh[ROWS * DIM], g_xl[ROWS * DIM];
__device__ __nv_bfloat16 g_wth[1536 * 256], g_wtl[1536 * 256];   // [n][k]
__device__ __nv_bfloat16 g_wpth[256 * 512], g_wptl[256 * 512];   // [n][k]
__device__ __nv_bfloat16 g_qh[BH * NSEQ * HD];
__device__ __nv_bfloat16 g_ql[BH * NSEQ * HD];
__device__ __nv_bfloat16 g_kh[BH * NSEQ * HD];
__device__ __nv_bfloat16 g_kl[BH * NSEQ * HD];
__device__ __nv_bfloat16 g_vth[BH * HD * NSEQ];   // transposed: [bh][d][n]
__device__ __nv_bfloat16 g_vtl[BH * HD * NSEQ];
__device__ __nv_bfloat16 g_attn_h[(size_t)BH * NSEQ * NSEQ];  // 64 MB
__device__ float g_oh[BH * NSEQ * HD];
__device__ float g_pes[BH * NSEQ * PEC];
__device__ __nv_bfloat16 g_mh[ROWS * EDIM], g_ml[ROWS * EDIM];

union B16x8 { __nv_bfloat16 h[8]; uint4 u; };
union B16x4 { __nv_bfloat16 h[4]; uint2 u; };
union B16x2 { __nv_bfloat16 h[2]; uint32_t u; };

__device__ __forceinline__ void split2(float x, __nv_bfloat16& h, __nv_bfloat16& l) {
  h = __float2bfloat16_rn(x);
  l = __float2bfloat16_rn(x - __bfloat162float(h));
}

// m16n8k16 bf16 mma with fp32 accumulate (row.col)
__device__ __forceinline__ void mma16816(float* c, const uint32_t* a,
                                         const uint32_t* b) {
  asm volatile(
      "mma.sync.aligned.m16n8k16.row.col.f32.bf16.bf16.f32 "
      "{%0,%1,%2,%3}, {%4,%5,%6,%7}, {%8,%9}, {%0,%1,%2,%3};"
      : "+f"(c[0]), "+f"(c[1]), "+f"(c[2]), "+f"(c[3])
      : "r"(a[0]), "r"(a[1]), "r"(a[2]), "r"(a[3]), "r"(b[0]), "r"(b[1]));
}

// ldmatrix x4: 4 8x8 b16 tiles; lane group g=lane>>3 supplies address of tile g
__device__ __forceinline__ void ldsm4(uint32_t* d, const __nv_bfloat16* p) {
  uint32_t a = (uint32_t)__cvta_generic_to_shared(p);
  asm volatile("ldmatrix.sync.aligned.m8n8.x4.shared.b16 {%0,%1,%2,%3}, [%4];"
               : "=r"(d[0]), "=r"(d[1]), "=r"(d[2]), "=r"(d[3]) : "r"(a));
}

// 16B async copy gmem -> smem
__device__ __forceinline__ void cp16(__nv_bfloat16* smem_ptr, const __nv_bfloat16* gptr) {
  uint32_t s = (uint32_t)__cvta_generic_to_shared(smem_ptr);
  asm volatile("cp.async.cg.shared.global [%0], [%1], 16;" :: "r"(s), "l"(gptr));
}
#define CP_COMMIT() asm volatile("cp.async.commit_group;" ::: "memory")
#define CP_WAIT1()  asm volatile("cp.async.wait_group 1;" ::: "memory")
#define CP_WAIT0()  asm volatile("cp.async.wait_group 0;" ::: "memory")

#define LDSTRIDE 72   // bf16 units per SMEM row (64 data + 8 pad)
#define PSTRIDE 136   // bf16 units per SMEM row (128 data + 8 pad)
#define GEMM_SMEM_BYTES ((2 * 128 + 2 * 64) * LDSTRIDE * 2)   // 55296

// ---------------- prep: split x into bf16 hi/lo ------------------------------
__global__ __launch_bounds__(256) void split_x(const float* __restrict__ x) {
  int idx = (blockIdx.x * 256 + threadIdx.x) * 4;
  float4 v = *(const float4*)(x + idx);
  B16x4 hh, ll;
  split2(v.x, hh.h[0], ll.h[0]); split2(v.y, hh.h[1], ll.h[1]);
  split2(v.z, hh.h[2], ll.h[2]); split2(v.w, hh.h[3], ll.h[3]);
  *(uint2*)&g_xh[idx] = hh.u;
  *(uint2*)&g_xl[idx] = ll.u;
}

// ---------------- prep: transpose + split weights -----------------------------
__global__ __launch_bounds__(256) void prep_w(
    const float* __restrict__ Wq, const float* __restrict__ Wk,
    const float* __restrict__ Wv, const float* __restrict__ Wproj) {
  int id = blockIdx.x * 256 + threadIdx.x;
  if (id < 98304) {                 // WT: 1536 n x 64 k-groups
    int n = id >> 6, k0 = (id & 63) * 4;
    int sel = n >> 9, col = n & 511;
    const float* W = (sel == 0) ? Wq : (sel == 1) ? Wk : Wv;
#pragma unroll
    for (int q = 0; q < 4; q++) {
      float v = W[(k0 + q) * 512 + col];
      split2(v, g_wth[n * 256 + k0 + q], g_wtl[n * 256 + k0 + q]);
    }
  } else {                          // WprojT: 256 n x 128 k-groups
    int id2 = id - 98304;
    int n = id2 >> 7, k0 = (id2 & 127) * 4;
#pragma unroll
    for (int q = 0; q < 4; q++) {
      float v = Wproj[(k0 + q) * 256 + n];
      split2(v, g_wpth[n * 512 + k0 + q], g_wptl[n * 512 + k0 + q]);
    }
  }
}

// ---------------- Kernel 1: QKV projection via mma.sync ---------------------
// M=4096, N=1536, K=256. CTA 128m x 64n, grid (32, 24). 8 warps: 4m x 2n.
__global__ __launch_bounds__(256) void qkv_mma(const float* __restrict__ bv) {
  extern __shared__ __nv_bfloat16 sm[];
  __nv_bfloat16* XH = sm;
  __nv_bfloat16* XL = XH + 128 * LDSTRIDE;
  __nv_bfloat16* WH = XL + 128 * LDSTRIDE;
  __nv_bfloat16* WL = WH + 64 * LDSTRIDE;

  int tid = threadIdx.x;
  int wid = tid >> 5, lane = tid & 31;
  int m0 = blockIdx.x * 128;
  int n0 = blockIdx.y * 64;
  int sel = n0 / 512;
  int e0 = n0 % 512;
  int h = e0 / 64;

  int m_w = (wid >> 1) * 32, n_w = (wid & 1) * 32;
  int r = lane >> 2;
  int g = lane >> 3, rw = lane & 7;

  float c[2][4][4];
#pragma unroll
  for (int mt = 0; mt < 2; mt++)
#pragma unroll
    for (int nt = 0; nt < 4; nt++)
#pragma unroll
      for (int e = 0; e < 4; e++) c[mt][nt][e] = 0.f;

  for (int ck = 0; ck < 4; ck++) {
    if (ck) __syncthreads();
#pragma unroll
    for (int t = 0; t < 4; t++) {
      int idx = tid + 256 * t;
      int rr = idx >> 3, seg = idx & 7;
      int so = rr * LDSTRIDE + seg * 8;
      size_t gs = (size_t)(m0 + rr) * 256 + ck * 64 + seg * 8;
      *(uint4*)(XH + so) = *(const uint4*)(g_xh + gs);
      *(uint4*)(XL + so) = *(const uint4*)(g_xl + gs);
    }
#pragma unroll
    for (int t = 0; t < 2; t++) {
      int idx = tid + 256 * t;
      int d = idx >> 3, seg = idx & 7;
      int so = d * LDSTRIDE + seg * 8;
      size_t gs = (size_t)(n0 + d) * 256 + ck * 64 + seg * 8;
      *(uint4*)(WH + so) = *(const uint4*)(g_wth + gs);
      *(uint4*)(WL + so) = *(const uint4*)(g_wtl + gs);
    }
    __syncthreads();
#pragma unroll
    for (int kb = 0; kb < 64; kb += 16) {
      uint32_t ah[2][4], al[2][4];
#pragma unroll
      for (int mt = 0; mt < 2; mt++) {
        ldsm4(ah[mt], XH + (m_w + mt * 16 + (g & 1) * 8 + rw) * LDSTRIDE + kb + (g >> 1) * 8);
        ldsm4(al[mt], XL + (m_w + mt * 16 + (g & 1) * 8 + rw) * LDSTRIDE + kb + (g >> 1) * 8);
      }
      uint32_t bh4[2][4], bl4[2][4];
#pragma unroll
      for (int p = 0; p < 2; p++) {
        ldsm4(bh4[p], WH + (n_w + p * 16 + (g >> 1) * 8 + rw) * LDSTRIDE + kb + (g & 1) * 8);
        ldsm4(bl4[p], WL + (n_w + p * 16 + (g >> 1) * 8 + rw) * LDSTRIDE + kb + (g & 1) * 8);
      }
#pragma unroll
      for (int mt = 0; mt < 2; mt++)
#pragma unroll
        for (int p = 0; p < 2; p++) {
          mma16816(c[mt][2 * p], ah[mt], bh4[p]);
          mma16816(c[mt][2 * p], ah[mt], bl4[p]);
          mma16816(c[mt][2 * p], al[mt], bh4[p]);
          mma16816(c[mt][2 * p + 1], ah[mt], bh4[p] + 2);
          mma16816(c[mt][2 * p + 1], ah[mt], bl4[p] + 2);
          mma16816(c[mt][2 * p + 1], al[mt], bh4[p] + 2);
        }
    }
  }

#pragma unroll
  for (int mt = 0; mt < 2; mt++) {
#pragma unroll
    for (int nt = 0; nt < 4; nt++) {
      int colw = n_w + nt * 8 + (lane & 3) * 2;   // 0..62, even
      int d = colw;                                // channel within head
      int e = e0 + colw;
#pragma unroll
      for (int half = 0; half < 2; half++) {
        int row = m0 + m_w + mt * 16 + r + half * 8;
        float v0 = c[mt][nt][half * 2 + 0];
        float v1 = c[mt][nt][half * 2 + 1];
        int b = row >> 10, n = row & 1023;
        int bh = b * 8 + h;
        if (sel == 0) {
          v0 *= 0.125f; v1 *= 0.125f;
          B16x2 hp, lp;
          split2(v0, hp.h[0], lp.h[0]); split2(v1, hp.h[1], lp.h[1]);
          size_t idx = ((size_t)bh * 1024 + n) * 64 + d;
          *(uint32_t*)&g_qh[idx] = hp.u;
          *(uint32_t*)&g_ql[idx] = lp.u;
        } else if (sel == 1) {
          B16x2 hp, lp;
          split2(v0, hp.h[0], lp.h[0]); split2(v1, hp.h[1], lp.h[1]);
          size_t idx = ((size_t)bh * 1024 + n) * 64 + d;
          *(uint32_t*)&g_kh[idx] = hp.u;
          *(uint32_t*)&g_kl[idx] = lp.u;
        } else {
          v0 += bv[e]; v1 += bv[e + 1];
          __nv_bfloat16 hh, ll;
          split2(v0, hh, ll);
          size_t i0v = ((size_t)bh * 64 + d) * 1024 + n;
          g_vth[i0v] = hh; g_vtl[i0v] = ll;
          split2(v1, hh, ll);
          size_t i1v = ((size_t)bh * 64 + d + 1) * 1024 + n;
          g_vth[i1v] = hh; g_vtl[i1v] = ll;
        }
      }
    }
  }
}

// ---------------- Kernel 2: fused scores + softmax (16-row CTAs) ------------
// 2-pass split (q hi+lo vs k hi), cp.async double-buffered K, ldmatrix.
// CTA = 16 query rows x FULL 1024 cols. grid (64, 32). 8 warps, 16 cols each.
// Epilogue writes attn-hi only.
#define KSTAGE (128 * LDSTRIDE)     // 9216 elements per K stage
#define SM_SMEM_BYTES ((2 * 16 * LDSTRIDE + 2 * KSTAGE) * 2)   // 41472 B
__global__ __launch_bounds__(256, 2) void scoresm() {
  extern __shared__ __nv_bfloat16 smd[];
  __nv_bfloat16* QH = smd;
  __nv_bfloat16* QL = QH + 16 * LDSTRIDE;
  __nv_bfloat16* KHb = QL + 16 * LDSTRIDE;   // 2 stages of KSTAGE
  __shared__ float red[16][8];

  int tid = threadIdx.x;
  int wid = tid >> 5, lane = tid & 31;
  int bh = blockIdx.y;
  int i0 = blockIdx.x * 16;

  const __nv_bfloat16* qh = g_qh + (size_t)bh * NSEQ * HD;
  const __nv_bfloat16* ql = g_ql + (size_t)bh * NSEQ * HD;
  const __nv_bfloat16* kh = g_kh + (size_t)bh * NSEQ * HD;

  // stage q (16 x 64, hi/lo): threads 0..127, one uint4 per array
  if (tid < 128) {
    int r = tid >> 3, seg = tid & 7;
    int so = r * LDSTRIDE + seg * 8;
    *(uint4*)(QH + so) = *(const uint4*)(qh + (i0 + r) * 64 + seg * 8);
    *(uint4*)(QL + so) = *(const uint4*)(ql + (i0 + r) * 64 + seg * 8);
  }
  // prefetch K chunk 0 into stage 0 (hi only)
#pragma unroll
  for (int t = 0; t < 4; t++) {
    int idx = tid + 256 * t;
    int rr = idx >> 3, seg = idx & 7;
    cp16(KHb + rr * LDSTRIDE + seg * 8, kh + rr * 64 + seg * 8);
  }
  CP_COMMIT();

  int nwb = wid * 16;               // each warp owns 16 cols per 128-chunk
  int r = lane >> 2;
  int g = lane >> 3, rw = lane & 7;

  uint32_t ah[4][4], al[4][4];
  float acc[8][2][4];
#pragma unroll
  for (int jc = 0; jc < 8; jc++)
#pragma unroll
    for (int nt = 0; nt < 2; nt++)
#pragma unroll
      for (int e = 0; e < 4; e++) acc[jc][nt][e] = 0.f;

#pragma unroll
  for (int jc = 0; jc < 8; jc++) {
    int st = jc & 1;
    if (jc < 7) {
      int sn = st ^ 1;
#pragma unroll
      for (int t = 0; t < 4; t++) {
        int idx = tid + 256 * t;
        int rr = idx >> 3, seg = idx & 7;
        cp16(KHb + sn * KSTAGE + rr * LDSTRIDE + seg * 8,
             kh + ((jc + 1) * 128 + rr) * 64 + seg * 8);
      }
      CP_COMMIT();
      CP_WAIT1();
    } else {
      CP_WAIT0();
    }
    __syncthreads();
    const __nv_bfloat16* KH = KHb + st * KSTAGE;
    if (jc == 0) {
      // hoist q frags (hi and lo) for all 4 k-steps via ldmatrix
#pragma unroll
      for (int kb = 0; kb < 4; kb++) {
        ldsm4(ah[kb], QH + ((g & 1) * 8 + rw) * LDSTRIDE + kb * 16 + (g >> 1) * 8);
        ldsm4(al[kb], QL + ((g & 1) * 8 + rw) * LDSTRIDE + kb * 16 + (g >> 1) * 8);
      }
    }
#pragma unroll
    for (int kb = 0; kb < 4; kb++) {
      uint32_t b4[4];
      ldsm4(b4, KH + (nwb + (g >> 1) * 8 + rw) * LDSTRIDE + kb * 16 + (g & 1) * 8);
      mma16816(acc[jc][0], ah[kb], b4);
      mma16816(acc[jc][0], al[kb], b4);
      mma16816(acc[jc][1], ah[kb], b4 + 2);
      mma16816(acc[jc][1], al[kb], b4 + 2);
    }
    __syncthreads();   // all warps done reading stage st before refill
  }

  // ---- row softmax across the full 1024 columns ----
  int r0 = r, r1 = r0 + 8;
  float m0 = -1e30f, m1 = -1e30f;
#pragma unroll
  for (int jc = 0; jc < 8; jc++)
#pragma unroll
    for (int nt = 0; nt < 2; nt++) {
      m0 = fmaxf(m0, fmaxf(acc[jc][nt][0], acc[jc][nt][1]));
      m1 = fmaxf(m1, fmaxf(acc[jc][nt][2], acc[jc][nt][3]));
    }
#pragma unroll
  for (int o = 1; o <= 2; o <<= 1) {
    m0 = fmaxf(m0, __shfl_xor_sync(~0u, m0, o));
    m1 = fmaxf(m1, __shfl_xor_sync(~0u, m1, o));
  }
  if ((lane & 3) == 0) { red[r0][wid] = m0; red[r1][wid] = m1; }
  __syncthreads();
#pragma unroll
  for (int q = 0; q < 8; q++) {
    m0 = fmaxf(m0, red[r0][q]);
    m1 = fmaxf(m1, red[r1][q]);
  }
  __syncthreads();

  float s0 = 0.f, s1 = 0.f;
#pragma unroll
  for (int jc = 0; jc < 8; jc++)
#pragma unroll
    for (int nt = 0; nt < 2; nt++) {
      acc[jc][nt][0] = __expf(acc[jc][nt][0] - m0);
      acc[jc][nt][1] = __expf(acc[jc][nt][1] - m0);
      acc[jc][nt][2] = __expf(acc[jc][nt][2] - m1);
      acc[jc][nt][3] = __expf(acc[jc][nt][3] - m1);
      s0 += acc[jc][nt][0] + acc[jc][nt][1];
      s1 += acc[jc][nt][2] + acc[jc][nt][3];
    }
#pragma unroll
  for (int o = 1; o <= 2; o <<= 1) {
    s0 += __shfl_xor_sync(~0u, s0, o);
    s1 += __shfl_xor_sync(~0u, s1, o);
  }
  if ((lane & 3) == 0) { red[r0][wid] = s0; red[r1][wid] = s1; }
  __syncthreads();
  s0 = 0.f; s1 = 0.f;
#pragma unroll
  for (int q = 0; q < 8; q++) { s0 += red[r0][q]; s1 += red[r1][q]; }
  float inv0 = 1.f / s0, inv1 = 1.f / s1;

  size_t base0 = (((size_t)bh << 10) + (i0 + r0)) << 10;
  size_t base1 = (((size_t)bh << 10) + (i0 + r1)) << 10;
#pragma unroll
  for (int jc = 0; jc < 8; jc++) {
#pragma unroll
    for (int nt = 0; nt < 2; nt++) {
      int col = jc * 128 + nwb + nt * 8 + (lane & 3) * 2;
      B16x2 hp;
      hp.h[0] = __float2bfloat16_rn(acc[jc][nt][0] * inv0);
      hp.h[1] = __float2bfloat16_rn(acc[jc][nt][1] * inv0);
      *(uint32_t*)(g_attn_h + base0 + col) = hp.u;
      hp.h[0] = __float2bfloat16_rn(acc[jc][nt][2] * inv1);
      hp.h[1] = __float2bfloat16_rn(acc[jc][nt][3] * inv1);
      *(uint32_t*)(g_attn_h + base1 + col) = hp.u;
    }
  }
}

// ---------------- Kernel 3: out_head = attn_hi @ (v_hi+v_lo) ---------------
// 2-pass, cp.async + ldmatrix, attn hi only. 2 CTAs/SM (73.7 KB smem).
#define AV_A (128 * LDSTRIDE)   // 9216
#define AV_V (64 * LDSTRIDE)    // 4608
#define AV_STAGE (AV_A + 2 * AV_V)       // 18432 elements per stage
#define AV_SMEM_BYTES (2 * AV_STAGE * 2) // 73728 B
__global__ __launch_bounds__(256, 2) void av_mma() {
  extern __shared__ __nv_bfloat16 smd[];

  int tid = threadIdx.x;
  int wid = tid >> 5, lane = tid & 31;
  int bh = blockIdx.y;
  int i0 = blockIdx.x * 128;

  const __nv_bfloat16* vth = g_vth + (size_t)bh * HD * NSEQ;
  const __nv_bfloat16* vtl = g_vtl + (size_t)bh * HD * NSEQ;

  int m_w = (wid >> 1) * 32;
  int n_w = (wid & 1) * 32;
  int r = lane >> 2;
  int g = lane >> 3, rw = lane & 7;

  float c[2][4][4];
#pragma unroll
  for (int mt = 0; mt < 2; mt++)
#pragma unroll
    for (int nt = 0; nt < 4; nt++)
#pragma unroll
      for (int e = 0; e < 4; e++) c[mt][nt][e] = 0.f;

  // prefetch chunk 0 into stage 0
#pragma unroll
  for (int t = 0; t < 4; t++) {
    int idx = tid + 256 * t;
    int rr = idx >> 3, seg = idx & 7;
    size_t gsrc = ((((size_t)bh << 10) + i0 + rr) << 10) + seg * 8;
    cp16(smd + rr * LDSTRIDE + seg * 8, g_attn_h + gsrc);
  }
#pragma unroll
  for (int t = 0; t < 2; t++) {
    int idx = tid + 256 * t;
    int d = idx >> 3, seg = idx & 7;
    int so = AV_A + d * LDSTRIDE + seg * 8;
    cp16(smd + so, vth + (size_t)d * 1024 + seg * 8);
    cp16(smd + AV_V + so, vtl + (size_t)d * 1024 + seg * 8);
  }
  CP_COMMIT();

  for (int ck = 0; ck < 16; ck++) {
    int st = ck & 1;
    if (ck < 15) {
      int sn = st ^ 1;
      __nv_bfloat16* base = smd + sn * AV_STAGE;
#pragma unroll
      for (int t = 0; t < 4; t++) {
        int idx = tid + 256 * t;
        int rr = idx >> 3, seg = idx & 7;
        size_t gsrc = ((((size_t)bh << 10) + i0 + rr) << 10) + (ck + 1) * 64 + seg * 8;
        cp16(base + rr * LDSTRIDE + seg * 8, g_attn_h + gsrc);
      }
#pragma unroll
      for (int t = 0; t < 2; t++) {
        int idx = tid + 256 * t;
        int d = idx >> 3, seg = idx & 7;
        int so = AV_A + d * LDSTRIDE + seg * 8;
        cp16(base + so, vth + (size_t)d * 1024 + (ck + 1) * 64 + seg * 8);
        cp16(base + AV_V + so, vtl + (size_t)d * 1024 + (ck + 1) * 64 + seg * 8);
      }
      CP_COMMIT();
      CP_WAIT1();
    } else {
      CP_WAIT0();
    }
    __syncthreads();
    const __nv_bfloat16* AHs = smd + st * AV_STAGE;
    const __nv_bfloat16* VHs = AHs + AV_A;
    const __nv_bfloat16* VLs = VHs + AV_V;

#pragma unroll
    for (int kb = 0; kb < 64; kb += 16) {
      uint32_t ah[2][4];
#pragma unroll
      for (int mt = 0; mt < 2; mt++)
        ldsm4(ah[mt], AHs + (m_w + mt * 16 + (g & 1) * 8 + rw) * LDSTRIDE + kb + (g >> 1) * 8);
      uint32_t bh4[2][4], bl4[2][4];
#pragma unroll
      for (int p = 0; p < 2; p++) {
        ldsm4(bh4[p], VHs + (n_w + p * 16 + (g >> 1) * 8 + rw) * LDSTRIDE + kb + (g & 1) * 8);
        ldsm4(bl4[p], VLs + (n_w + p * 16 + (g >> 1) * 8 + rw) * LDSTRIDE + kb + (g & 1) * 8);
      }
#pragma unroll
      for (int mt = 0; mt < 2; mt++)
#pragma unroll
        for (int p = 0; p < 2; p++) {
          mma16816(c[mt][2 * p], ah[mt], bh4[p]);
          mma16816(c[mt][2 * p], ah[mt], bl4[p]);
          mma16816(c[mt][2 * p + 1], ah[mt], bh4[p] + 2);
          mma16816(c[mt][2 * p + 1], ah[mt], bl4[p] + 2);
        }
    }
    __syncthreads();
  }

#pragma unroll
  for (int mt = 0; mt < 2; mt++) {
#pragma unroll
    for (int nt = 0; nt < 4; nt++) {
      int row = i0 + m_w + mt * 16 + r;
      int col = n_w + nt * 8 + (lane & 3) * 2;
      float* dst = g_oh + ((size_t)bh * 1024 + row) * 64 + col;
      *(float2*)dst = make_float2(c[mt][nt][0], c[mt][nt][1]);
      *(float2*)(dst + 8 * 64) = make_float2(c[mt][nt][2], c[mt][nt][3]);
    }
  }
}

// ---------------- Kernel 4: pe_sum via mma (attn hi x pe hi, 1-pass) --------
__global__ __launch_bounds__(256) void pes_mma(const float* __restrict__ pe) {
  __shared__ __nv_bfloat16 AH[32 * PSTRIDE];
  __shared__ __nv_bfloat16 PH[32 * PSTRIDE];

  int tid = threadIdx.x;
  int wid = tid >> 5, lane = tid & 31;
  int i = blockIdx.x;
  int mw = (wid & 1) * 16;        // bh rows
  int nw = (wid >> 1) * 8;        // c cols
  int r = lane >> 2, kq = (lane & 3) * 2;

  float acc[4] = {};
  for (int kc = 0; kc < 8; kc++) {
    if (kc) __syncthreads();
#pragma unroll
    for (int t = 0; t < 2; t++) {
      int idx = tid + 256 * t;
      int row = idx >> 4, seg = idx & 15;
      size_t gsrc = ((size_t)row << 20) + ((size_t)i << 10) + kc * 128 + seg * 8;
      int so = row * PSTRIDE + seg * 8;
      *(uint4*)(AH + so) = *(const uint4*)(g_attn_h + gsrc);
    }
    // stage pe[i] chunk transposed (hi only): peT[c][j]
#pragma unroll
    for (int t = 0; t < 4; t++) {
      int idx = tid + 256 * t;
      int j = idx >> 3, c4 = idx & 7;
      float4 v = *(const float4*)(
          pe + (((size_t)i << 10) + kc * 128 + j) * 32 + c4 * 4);
      PH[(c4 * 4 + 0) * PSTRIDE + j] = __float2bfloat16_rn(v.x);
      PH[(c4 * 4 + 1) * PSTRIDE + j] = __float2bfloat16_rn(v.y);
      PH[(c4 * 4 + 2) * PSTRIDE + j] = __float2bfloat16_rn(v.z);
      PH[(c4 * 4 + 3) * PSTRIDE + j] = __float2bfloat16_rn(v.w);
    }
    __syncthreads();
#pragma unroll
    for (int kb = 0; kb < 8; kb++) {
      const __nv_bfloat16* p = AH + (mw + r) * PSTRIDE + kb * 16 + kq;
      uint32_t ah4[4] = {*(const uint32_t*)p,
                         *(const uint32_t*)(p + 8 * PSTRIDE),
                         *(const uint32_t*)(p + 8),
                         *(const uint32_t*)(p + 8 * PSTRIDE + 8)};
      const __nv_bfloat16* pb = PH + (nw + r) * PSTRIDE + kb * 16 + kq;
      uint32_t bh2[2] = {*(const uint32_t*)pb, *(const uint32_t*)(pb + 8)};
      mma16816(acc, ah4, bh2);
    }
  }
  int c = nw + (lane & 3) * 2;
  int b0 = mw + r, b1 = b0 + 8;
  *(float2*)&g_pes[(((size_t)b0 << 10) + i) * 32 + c] = make_float2(acc[0], acc[1]);
  *(float2*)&g_pes[(((size_t)b1 << 10) + i) * 32 + c] = make_float2(acc[2], acc[3]);
}

// ---------------- Kernel 5: merged = out_head + pe_sum@Wpe + bpe (split) ----
__global__ __launch_bounds__(256) void merge_kernel(
    const float* __restrict__ Wpe, const float* __restrict__ bpe) {
  __shared__ float wpe_s[32 * 64];
  __shared__ float pes_s[32 * 32];
  __shared__ float bpe_s[64];
  int bh = blockIdx.x;
  int n0 = blockIdx.y * 32;
  int tid = threadIdx.x;
#pragma unroll
  for (int r = 0; r < 8; r++) wpe_s[tid + r * 256] = Wpe[tid + r * 256];
  if (tid < 64) bpe_s[tid] = bpe[tid];
  {
    int nl = tid >> 3, cc = tid & 7;
    *(float4*)&pes_s[nl * 32 + cc * 4] =
        *(const float4*)(g_pes + ((size_t)bh * 1024 + n0 + nl) * 32 + cc * 4);
  }
  __syncthreads();
  int nl = tid >> 3;
  int d0 = (tid & 7) * 8;
  int b = bh >> 3, h = bh & 7;
  const float* ohp = g_oh + ((size_t)bh * 1024 + n0 + nl) * 64 + d0;
  float o[8];
#pragma unroll
  for (int dd = 0; dd < 8; dd++) o[dd] = bpe_s[d0 + dd] + ohp[dd];
#pragma unroll 8
  for (int c = 0; c < 32; c++) {
    float pv = pes_s[nl * 32 + c];
#pragma unroll
    for (int dd = 0; dd < 8; dd++) o[dd] += pv * wpe_s[c * 64 + d0 + dd];
  }
  size_t mp = ((size_t)(b * 1024 + n0 + nl)) * 512 + h * 64 + d0;
  B16x8 hh, ll;
#pragma unroll
  for (int dd = 0; dd < 8; dd++) split2(o[dd], hh.h[dd], ll.h[dd]);
  *(uint4*)&g_mh[mp] = hh.u;
  *(uint4*)&g_ml[mp] = ll.u;
}

// ---------------- Kernel 6: out = merged @ Wproj via mma.sync ----------------
// M=4096, N=256, K=512. CTA 128m x 64n, grid (32, 4).
__global__ __launch_bounds__(256) void proj_mma(float* __restrict__ out) {
  extern __shared__ __nv_bfloat16 sm[];
  __nv_bfloat16* MH = sm;
  __nv_bfloat16* ML = MH + 128 * LDSTRIDE;
  __nv_bfloat16* WH = ML + 128 * LDSTRIDE;
  __nv_bfloat16* WL = WH + 64 * LDSTRIDE;

  int tid = threadIdx.x;
  int wid = tid >> 5, lane = tid & 31;
  int m0 = blockIdx.x * 128;
  int n0 = blockIdx.y * 64;

  int m_w = (wid >> 1) * 32, n_w = (wid & 1) * 32;
  int r = lane >> 2;
  int g = lane >> 3, rw = lane & 7;

  float c[2][4][4];
#pragma unroll
  for (int mt = 0; mt < 2; mt++)
#pragma unroll
    for (int nt = 0; nt < 4; nt++)
#pragma unroll
      for (int e = 0; e < 4; e++) c[mt][nt][e] = 0.f;

  for (int ck = 0; ck < 8; ck++) {
    if (ck) __syncthreads();
#pragma unroll
    for (int t = 0; t < 4; t++) {
      int idx = tid + 256 * t;
      int rr = idx >> 3, seg = idx & 7;
      int so = rr * LDSTRIDE + seg * 8;
      size_t gs = (size_t)(m0 + rr) * 512 + ck * 64 + seg * 8;
      *(uint4*)(MH + so) = *(const uint4*)(g_mh + gs);
      *(uint4*)(ML + so) = *(const uint4*)(g_ml + gs);
    }
#pragma unroll
    for (int t = 0; t < 2; t++) {
      int idx = tid + 256 * t;
      int d = idx >> 3, seg = idx & 7;
      int so = d * LDSTRIDE + seg * 8;
      size_t gs = (size_t)(n0 + d) * 512 + ck * 64 + seg * 8;
      *(uint4*)(WH + so) = *(const uint4*)(g_wpth + gs);
      *(uint4*)(WL + so) = *(const uint4*)(g_wptl + gs);
    }
    __syncthreads();
#pragma unroll
    for (int kb = 0; kb < 64; kb += 16) {
      uint32_t ah[2][4], al[2][4];
#pragma unroll
      for (int mt = 0; mt < 2; mt++) {
        ldsm4(ah[mt], MH + (m_w + mt * 16 + (g & 1) * 8 + rw) * LDSTRIDE + kb + (g >> 1) * 8);
        ldsm4(al[mt], ML + (m_w + mt * 16 + (g & 1) * 8 + rw) * LDSTRIDE + kb + (g >> 1) * 8);
      }
      uint32_t bh4[2][4], bl4[2][4];
#pragma unroll
      for (int p = 0; p < 2; p++) {
        ldsm4(bh4[p], WH + (n_w + p * 16 + (g >> 1) * 8 + rw) * LDSTRIDE + kb + (g & 1) * 8);
        ldsm4(bl4[p], WL + (n_w + p * 16 + (g >> 1) * 8 + rw) * LDSTRIDE + kb + (g & 1) * 8);
      }
#pragma unroll
      for (int mt = 0; mt < 2; mt++)
#pragma unroll
        for (int p = 0; p < 2; p++) {
          mma16816(c[mt][2 * p], ah[mt], bh4[p]);
          mma16816(c[mt][2 * p], ah[mt], bl4[p]);
          mma16816(c[mt][2 * p], al[mt], bh4[p]);
          mma16816(c[mt][2 * p + 1], ah[mt], bh4[p] + 2);
          mma16816(c[mt][2 * p + 1], ah[mt], bl4[p] + 2);
          mma16816(c[mt][2 * p + 1], al[mt], bh4[p] + 2);
        }
    }
  }

#pragma unroll
  for (int mt = 0; mt < 2; mt++) {
#pragma unroll
    for (int nt = 0; nt < 4; nt++) {
      int row = m0 + m_w + mt * 16 + r;
      int col = n0 + n_w + nt * 8 + (lane & 3) * 2;
      float* dst = out + (size_t)row * 256 + col;
      *(float2*)dst = make_float2(c[mt][nt][0], c[mt][nt][1]);
      *(float2*)(dst + 8 * 256) = make_float2(c[mt][nt][2], c[mt][nt][3]);
    }
  }
}

// ---------------- launch -----------------------------------------------------
extern "C" void kernel_launch(void* const* d_in, const int* in_sizes, int n_in,
                              void* d_out, int out_size) {
  const float* x     = (const float*)d_in[0];
  const float* pe    = (const float*)d_in[1];
  const float* Wq    = (const float*)d_in[2];
  const float* Wk    = (const float*)d_in[3];
  const float* Wv    = (const float*)d_in[4];
  const float* bv    = (const float*)d_in[5];
  const float* Wpe   = (const float*)d_in[6];
  const float* bpe   = (const float*)d_in[7];
  const float* Wproj = (const float*)d_in[8];
  float* out = (float*)d_out;

  cudaFuncSetAttribute(qkv_mma, cudaFuncAttributeMaxDynamicSharedMemorySize,
                       GEMM_SMEM_BYTES);
  cudaFuncSetAttribute(scoresm, cudaFuncAttributeMaxDynamicSharedMemorySize,
                       SM_SMEM_BYTES);
  cudaFuncSetAttribute(av_mma, cudaFuncAttributeMaxDynamicSharedMemorySize,
                       AV_SMEM_BYTES);
  cudaFuncSetAttribute(proj_mma, cudaFuncAttributeMaxDynamicSharedMemorySize,
                       GEMM_SMEM_BYTES);

  split_x<<<1024, 256>>>(x);
  prep_w<<<512, 256>>>(Wq, Wk, Wv, Wproj);
  qkv_mma<<<dim3(32, 24), 256, GEMM_SMEM_BYTES>>>(bv);
  scoresm<<<dim3(64, 32), 256, SM_SMEM_BYTES>>>();
  av_mma<<<dim3(8, 32), 256, AV_SMEM_BYTES>>>();
  pes_mma<<<1024, 256>>>(pe);
  merge_kernel<<<dim3(32, 32), 256>>>(Wpe, bpe);
  proj_mma<<<dim3(32, 4), 256, GEMM_SMEM_BYTES>>>(out);
}

// round 13
// speedup vs baseline: 1.3576x; 1.0294x over previous
#include <cuda_runtime.h>
#include <cuda_bf16.h>
#include <cstdint>

#define NSEQ 1024
#define DIM  256
#define HEADS 8
#define EDIM 512
#define HD   64
#define PEC  32
#define BH   32           // B*HEADS
#define ROWS 4096         // B*N

// ---------------- scratch (device globals; no runtime allocation) ----------
__device__ __nv_bfloat16 g_xh[ROWS * DIM], g_xl[ROWS * DIM];
__device__ __nv_bfloat16 g_wth[1536 * 256], g_wtl[1536 * 256];   // [n][k]
__device__ __nv_bfloat16 g_wpth[256 * 512], g_wptl[256 * 512];   // [n][k]
__device__ __nv_bfloat16 g_qh[BH * NSEQ * HD];
__device__ __nv_bfloat16 g_ql[BH * NSEQ * HD];
__device__ __nv_bfloat16 g_kh[BH * NSEQ * HD];
__device__ __nv_bfloat16 g_kl[BH * NSEQ * HD];
__device__ __nv_bfloat16 g_vth[BH * HD * NSEQ];   // transposed: [bh][d][n]
__device__ __nv_bfloat16 g_vtl[BH * HD * NSEQ];
__device__ __nv_bfloat16 g_attn_h[(size_t)BH * NSEQ * NSEQ];  // 64 MB
__device__ float g_oh[BH * NSEQ * HD];
__device__ float g_pes[BH * NSEQ * PEC];
__device__ __nv_bfloat16 g_mh[ROWS * EDIM], g_ml[ROWS * EDIM];

union B16x8 { __nv_bfloat16 h[8]; uint4 u; };
union B16x4 { __nv_bfloat16 h[4]; uint2 u; };
union B16x2 { __nv_bfloat16 h[2]; uint32_t u; };

__device__ __forceinline__ void split2(float x, __nv_bfloat16& h, __nv_bfloat16& l) {
  h = __float2bfloat16_rn(x);
  l = __float2bfloat16_rn(x - __bfloat162float(h));
}

// m16n8k16 bf16 mma with fp32 accumulate (row.col)
__device__ __forceinline__ void mma16816(float* c, const uint32_t* a,
                                         const uint32_t* b) {
  asm volatile(
      "mma.sync.aligned.m16n8k16.row.col.f32.bf16.bf16.f32 "
      "{%0,%1,%2,%3}, {%4,%5,%6,%7}, {%8,%9}, {%0,%1,%2,%3};"
      : "+f"(c[0]), "+f"(c[1]), "+f"(c[2]), "+f"(c[3])
      : "r"(a[0]), "r"(a[1]), "r"(a[2]), "r"(a[3]), "r"(b[0]), "r"(b[1]));
}

// ldmatrix x4: 4 8x8 b16 tiles; lane group g=lane>>3 supplies address of tile g
__device__ __forceinline__ void ldsm4(uint32_t* d, const __nv_bfloat16* p) {
  uint32_t a = (uint32_t)__cvta_generic_to_shared(p);
  asm volatile("ldmatrix.sync.aligned.m8n8.x4.shared.b16 {%0,%1,%2,%3}, [%4];"
               : "=r"(d[0]), "=r"(d[1]), "=r"(d[2]), "=r"(d[3]) : "r"(a));
}

// 16B async copy gmem -> smem
__device__ __forceinline__ void cp16(__nv_bfloat16* smem_ptr, const __nv_bfloat16* gptr) {
  uint32_t s = (uint32_t)__cvta_generic_to_shared(smem_ptr);
  asm volatile("cp.async.cg.shared.global [%0], [%1], 16;" :: "r"(s), "l"(gptr));
}
#define CP_COMMIT() asm volatile("cp.async.commit_group;" ::: "memory")
#define CP_WAIT1()  asm volatile("cp.async.wait_group 1;" ::: "memory")
#define CP_WAIT0()  asm volatile("cp.async.wait_group 0;" ::: "memory")

#define LDSTRIDE 72   // bf16 units per SMEM row (64 data + 8 pad)
#define PSTRIDE 136   // bf16 units per SMEM row (128 data + 8 pad)
#define GEMM_SMEM_BYTES ((2 * 128 + 2 * 64) * LDSTRIDE * 2)   // 55296

// ---------------- prep: split x into bf16 hi/lo ------------------------------
__global__ __launch_bounds__(256) void split_x(const float* __restrict__ x) {
  int idx = (blockIdx.x * 256 + threadIdx.x) * 4;
  float4 v = *(const float4*)(x + idx);
  B16x4 hh, ll;
  split2(v.x, hh.h[0], ll.h[0]); split2(v.y, hh.h[1], ll.h[1]);
  split2(v.z, hh.h[2], ll.h[2]); split2(v.w, hh.h[3], ll.h[3]);
  *(uint2*)&g_xh[idx] = hh.u;
  *(uint2*)&g_xl[idx] = ll.u;
}

// ---------------- prep: transpose + split weights -----------------------------
__global__ __launch_bounds__(256) void prep_w(
    const float* __restrict__ Wq, const float* __restrict__ Wk,
    const float* __restrict__ Wv, const float* __restrict__ Wproj) {
  int id = blockIdx.x * 256 + threadIdx.x;
  if (id < 98304) {                 // WT: 1536 n x 64 k-groups
    int n = id >> 6, k0 = (id & 63) * 4;
    int sel = n >> 9, col = n & 511;
    const float* W = (sel == 0) ? Wq : (sel == 1) ? Wk : Wv;
#pragma unroll
    for (int q = 0; q < 4; q++) {
      float v = W[(k0 + q) * 512 + col];
      split2(v, g_wth[n * 256 + k0 + q], g_wtl[n * 256 + k0 + q]);
    }
  } else {                          // WprojT: 256 n x 128 k-groups
    int id2 = id - 98304;
    int n = id2 >> 7, k0 = (id2 & 127) * 4;
#pragma unroll
    for (int q = 0; q < 4; q++) {
      float v = Wproj[(k0 + q) * 256 + n];
      split2(v, g_wpth[n * 512 + k0 + q], g_wptl[n * 512 + k0 + q]);
    }
  }
}

// ---------------- Kernel 1: QKV projection via mma.sync ---------------------
// M=4096, N=1536, K=256. CTA 128m x 64n, grid (32, 24). 8 warps: 4m x 2n.
__global__ __launch_bounds__(256) void qkv_mma(const float* __restrict__ bv) {
  extern __shared__ __nv_bfloat16 sm[];
  __nv_bfloat16* XH = sm;
  __nv_bfloat16* XL = XH + 128 * LDSTRIDE;
  __nv_bfloat16* WH = XL + 128 * LDSTRIDE;
  __nv_bfloat16* WL = WH + 64 * LDSTRIDE;

  int tid = threadIdx.x;
  int wid = tid >> 5, lane = tid & 31;
  int m0 = blockIdx.x * 128;
  int n0 = blockIdx.y * 64;
  int sel = n0 / 512;
  int e0 = n0 % 512;
  int h = e0 / 64;

  int m_w = (wid >> 1) * 32, n_w = (wid & 1) * 32;
  int r = lane >> 2;
  int g = lane >> 3, rw = lane & 7;

  float c[2][4][4];
#pragma unroll
  for (int mt = 0; mt < 2; mt++)
#pragma unroll
    for (int nt = 0; nt < 4; nt++)
#pragma unroll
      for (int e = 0; e < 4; e++) c[mt][nt][e] = 0.f;

  for (int ck = 0; ck < 4; ck++) {
    if (ck) __syncthreads();
#pragma unroll
    for (int t = 0; t < 4; t++) {
      int idx = tid + 256 * t;
      int rr = idx >> 3, seg = idx & 7;
      int so = rr * LDSTRIDE + seg * 8;
      size_t gs = (size_t)(m0 + rr) * 256 + ck * 64 + seg * 8;
      *(uint4*)(XH + so) = *(const uint4*)(g_xh + gs);
      *(uint4*)(XL + so) = *(const uint4*)(g_xl + gs);
    }
#pragma unroll
    for (int t = 0; t < 2; t++) {
      int idx = tid + 256 * t;
      int d = idx >> 3, seg = idx & 7;
      int so = d * LDSTRIDE + seg * 8;
      size_t gs = (size_t)(n0 + d) * 256 + ck * 64 + seg * 8;
      *(uint4*)(WH + so) = *(const uint4*)(g_wth + gs);
      *(uint4*)(WL + so) = *(const uint4*)(g_wtl + gs);
    }
    __syncthreads();
#pragma unroll
    for (int kb = 0; kb < 64; kb += 16) {
      uint32_t ah[2][4], al[2][4];
#pragma unroll
      for (int mt = 0; mt < 2; mt++) {
        ldsm4(ah[mt], XH + (m_w + mt * 16 + (g & 1) * 8 + rw) * LDSTRIDE + kb + (g >> 1) * 8);
        ldsm4(al[mt], XL + (m_w + mt * 16 + (g & 1) * 8 + rw) * LDSTRIDE + kb + (g >> 1) * 8);
      }
      uint32_t bh4[2][4], bl4[2][4];
#pragma unroll
      for (int p = 0; p < 2; p++) {
        ldsm4(bh4[p], WH + (n_w + p * 16 + (g >> 1) * 8 + rw) * LDSTRIDE + kb + (g & 1) * 8);
        ldsm4(bl4[p], WL + (n_w + p * 16 + (g >> 1) * 8 + rw) * LDSTRIDE + kb + (g & 1) * 8);
      }
#pragma unroll
      for (int mt = 0; mt < 2; mt++)
#pragma unroll
        for (int p = 0; p < 2; p++) {
          mma16816(c[mt][2 * p], ah[mt], bh4[p]);
          mma16816(c[mt][2 * p], ah[mt], bl4[p]);
          mma16816(c[mt][2 * p], al[mt], bh4[p]);
          mma16816(c[mt][2 * p + 1], ah[mt], bh4[p] + 2);
          mma16816(c[mt][2 * p + 1], ah[mt], bl4[p] + 2);
          mma16816(c[mt][2 * p + 1], al[mt], bh4[p] + 2);
        }
    }
  }

#pragma unroll
  for (int mt = 0; mt < 2; mt++) {
#pragma unroll
    for (int nt = 0; nt < 4; nt++) {
      int colw = n_w + nt * 8 + (lane & 3) * 2;   // 0..62, even
      int d = colw;                                // channel within head
      int e = e0 + colw;
#pragma unroll
      for (int half = 0; half < 2; half++) {
        int row = m0 + m_w + mt * 16 + r + half * 8;
        float v0 = c[mt][nt][half * 2 + 0];
        float v1 = c[mt][nt][half * 2 + 1];
        int b = row >> 10, n = row & 1023;
        int bh = b * 8 + h;
        if (sel == 0) {
          v0 *= 0.125f; v1 *= 0.125f;
          B16x2 hp, lp;
          split2(v0, hp.h[0], lp.h[0]); split2(v1, hp.h[1], lp.h[1]);
          size_t idx = ((size_t)bh * 1024 + n) * 64 + d;
          *(uint32_t*)&g_qh[idx] = hp.u;
          *(uint32_t*)&g_ql[idx] = lp.u;
        } else if (sel == 1) {
          B16x2 hp, lp;
          split2(v0, hp.h[0], lp.h[0]); split2(v1, hp.h[1], lp.h[1]);
          size_t idx = ((size_t)bh * 1024 + n) * 64 + d;
          *(uint32_t*)&g_kh[idx] = hp.u;
          *(uint32_t*)&g_kl[idx] = lp.u;
        } else {
          v0 += bv[e]; v1 += bv[e + 1];
          __nv_bfloat16 hh, ll;
          split2(v0, hh, ll);
          size_t i0v = ((size_t)bh * 64 + d) * 1024 + n;
          g_vth[i0v] = hh; g_vtl[i0v] = ll;
          split2(v1, hh, ll);
          size_t i1v = ((size_t)bh * 64 + d + 1) * 1024 + n;
          g_vth[i1v] = hh; g_vtl[i1v] = ll;
        }
      }
    }
  }
}

// ---------------- Kernel 2: fused scores + softmax (16-row CTAs) ------------
// 2-pass split (q hi+lo vs k hi), cp.async double-buffered K, ldmatrix.
// CTA = 16 query rows x FULL 1024 cols. grid (64, 32). 8 warps, 16 cols each.
// Epilogue writes attn-hi only.
#define KSTAGE (128 * LDSTRIDE)     // 9216 elements per K stage
#define SM_SMEM_BYTES ((2 * 16 * LDSTRIDE + 2 * KSTAGE) * 2)   // 41472 B
__global__ __launch_bounds__(256, 2) void scoresm() {
  extern __shared__ __nv_bfloat16 smd[];
  __nv_bfloat16* QH = smd;
  __nv_bfloat16* QL = QH + 16 * LDSTRIDE;
  __nv_bfloat16* KHb = QL + 16 * LDSTRIDE;   // 2 stages of KSTAGE
  __shared__ float red[16][8];

  int tid = threadIdx.x;
  int wid = tid >> 5, lane = tid & 31;
  int bh = blockIdx.y;
  int i0 = blockIdx.x * 16;

  const __nv_bfloat16* qh = g_qh + (size_t)bh * NSEQ * HD;
  const __nv_bfloat16* ql = g_ql + (size_t)bh * NSEQ * HD;
  const __nv_bfloat16* kh = g_kh + (size_t)bh * NSEQ * HD;

  // stage q (16 x 64, hi/lo): threads 0..127, one uint4 per array
  if (tid < 128) {
    int r = tid >> 3, seg = tid & 7;
    int so = r * LDSTRIDE + seg * 8;
    *(uint4*)(QH + so) = *(const uint4*)(qh + (i0 + r) * 64 + seg * 8);
    *(uint4*)(QL + so) = *(const uint4*)(ql + (i0 + r) * 64 + seg * 8);
  }
  // prefetch K chunk 0 into stage 0 (hi only)
#pragma unroll
  for (int t = 0; t < 4; t++) {
    int idx = tid + 256 * t;
    int rr = idx >> 3, seg = idx & 7;
    cp16(KHb + rr * LDSTRIDE + seg * 8, kh + rr * 64 + seg * 8);
  }
  CP_COMMIT();

  int nwb = wid * 16;               // each warp owns 16 cols per 128-chunk
  int r = lane >> 2;
  int g = lane >> 3, rw = lane & 7;

  uint32_t ah[4][4], al[4][4];
  float acc[8][2][4];
#pragma unroll
  for (int jc = 0; jc < 8; jc++)
#pragma unroll
    for (int nt = 0; nt < 2; nt++)
#pragma unroll
      for (int e = 0; e < 4; e++) acc[jc][nt][e] = 0.f;

#pragma unroll
  for (int jc = 0; jc < 8; jc++) {
    int st = jc & 1;
    if (jc < 7) {
      int sn = st ^ 1;
#pragma unroll
      for (int t = 0; t < 4; t++) {
        int idx = tid + 256 * t;
        int rr = idx >> 3, seg = idx & 7;
        cp16(KHb + sn * KSTAGE + rr * LDSTRIDE + seg * 8,
             kh + ((jc + 1) * 128 + rr) * 64 + seg * 8);
      }
      CP_COMMIT();
      CP_WAIT1();
    } else {
      CP_WAIT0();
    }
    __syncthreads();
    const __nv_bfloat16* KH = KHb + st * KSTAGE;
    if (jc == 0) {
      // hoist q frags (hi and lo) for all 4 k-steps via ldmatrix
#pragma unroll
      for (int kb = 0; kb < 4; kb++) {
        ldsm4(ah[kb], QH + ((g & 1) * 8 + rw) * LDSTRIDE + kb * 16 + (g >> 1) * 8);
        ldsm4(al[kb], QL + ((g & 1) * 8 + rw) * LDSTRIDE + kb * 16 + (g >> 1) * 8);
      }
    }
#pragma unroll
    for (int kb = 0; kb < 4; kb++) {
      uint32_t b4[4];
      ldsm4(b4, KH + (nwb + (g >> 1) * 8 + rw) * LDSTRIDE + kb * 16 + (g & 1) * 8);
      mma16816(acc[jc][0], ah[kb], b4);
      mma16816(acc[jc][0], al[kb], b4);
      mma16816(acc[jc][1], ah[kb], b4 + 2);
      mma16816(acc[jc][1], al[kb], b4 + 2);
    }
    __syncthreads();   // all warps done reading stage st before refill
  }

  // ---- row softmax across the full 1024 columns ----
  int r0 = r, r1 = r0 + 8;
  float m0 = -1e30f, m1 = -1e30f;
#pragma unroll
  for (int jc = 0; jc < 8; jc++)
#pragma unroll
    for (int nt = 0; nt < 2; nt++) {
      m0 = fmaxf(m0, fmaxf(acc[jc][nt][0], acc[jc][nt][1]));
      m1 = fmaxf(m1, fmaxf(acc[jc][nt][2], acc[jc][nt][3]));
    }
#pragma unroll
  for (int o = 1; o <= 2; o <<= 1) {
    m0 = fmaxf(m0, __shfl_xor_sync(~0u, m0, o));
    m1 = fmaxf(m1, __shfl_xor_sync(~0u, m1, o));
  }
  if ((lane & 3) == 0) { red[r0][wid] = m0; red[r1][wid] = m1; }
  __syncthreads();
#pragma unroll
  for (int q = 0; q < 8; q++) {
    m0 = fmaxf(m0, red[r0][q]);
    m1 = fmaxf(m1, red[r1][q]);
  }
  __syncthreads();

  float s0 = 0.f, s1 = 0.f;
#pragma unroll
  for (int jc = 0; jc < 8; jc++)
#pragma unroll
    for (int nt = 0; nt < 2; nt++) {
      acc[jc][nt][0] = __expf(acc[jc][nt][0] - m0);
      acc[jc][nt][1] = __expf(acc[jc][nt][1] - m0);
      acc[jc][nt][2] = __expf(acc[jc][nt][2] - m1);
      acc[jc][nt][3] = __expf(acc[jc][nt][3] - m1);
      s0 += acc[jc][nt][0] + acc[jc][nt][1];
      s1 += acc[jc][nt][2] + acc[jc][nt][3];
    }
#pragma unroll
  for (int o = 1; o <= 2; o <<= 1) {
    s0 += __shfl_xor_sync(~0u, s0, o);
    s1 += __shfl_xor_sync(~0u, s1, o);
  }
  if ((lane & 3) == 0) { red[r0][wid] = s0; red[r1][wid] = s1; }
  __syncthreads();
  s0 = 0.f; s1 = 0.f;
#pragma unroll
  for (int q = 0; q < 8; q++) { s0 += red[r0][q]; s1 += red[r1][q]; }
  float inv0 = 1.f / s0, inv1 = 1.f / s1;

  size_t base0 = (((size_t)bh << 10) + (i0 + r0)) << 10;
  size_t base1 = (((size_t)bh << 10) + (i0 + r1)) << 10;
#pragma unroll
  for (int jc = 0; jc < 8; jc++) {
#pragma unroll
    for (int nt = 0; nt < 2; nt++) {
      int col = jc * 128 + nwb + nt * 8 + (lane & 3) * 2;
      B16x2 hp;
      hp.h[0] = __float2bfloat16_rn(acc[jc][nt][0] * inv0);
      hp.h[1] = __float2bfloat16_rn(acc[jc][nt][1] * inv0);
      *(uint32_t*)(g_attn_h + base0 + col) = hp.u;
      hp.h[0] = __float2bfloat16_rn(acc[jc][nt][2] * inv1);
      hp.h[1] = __float2bfloat16_rn(acc[jc][nt][3] * inv1);
      *(uint32_t*)(g_attn_h + base1 + col) = hp.u;
    }
  }
}

// ---------------- Kernel 3: FUSED av + pes (grid concatenation) -------------
// Blocks [0,256): out_head = attn_hi @ (v_hi+v_lo), 2-pass, cp.async+ldmatrix.
// Blocks [256,1280): pe_sum = attn_hi @ pe_hi, cp.async attn + reg-prefetch pe.
#define AV_A (128 * LDSTRIDE)   // 9216
#define AV_V (64 * LDSTRIDE)    // 4608
#define AV_STAGE (AV_A + 2 * AV_V)       // 18432 elements per stage
#define AVP_SMEM_BYTES (2 * AV_STAGE * 2) // 73728 B (covers pes' 4x32*PSTRIDE too)
__global__ __launch_bounds__(256, 2) void avpes(const float* __restrict__ pe) {
  extern __shared__ __nv_bfloat16 smd[];
  int tid = threadIdx.x;
  int wid = tid >> 5, lane = tid & 31;

  if (blockIdx.x < 256) {
    // =================== AV body ===================
    int bh = blockIdx.x >> 3;
    int i0 = (blockIdx.x & 7) * 128;

    const __nv_bfloat16* vth = g_vth + (size_t)bh * HD * NSEQ;
    const __nv_bfloat16* vtl = g_vtl + (size_t)bh * HD * NSEQ;

    int m_w = (wid >> 1) * 32;
    int n_w = (wid & 1) * 32;
    int r = lane >> 2;
    int g = lane >> 3, rw = lane & 7;

    float c[2][4][4];
#pragma unroll
    for (int mt = 0; mt < 2; mt++)
#pragma unroll
      for (int nt = 0; nt < 4; nt++)
#pragma unroll
        for (int e = 0; e < 4; e++) c[mt][nt][e] = 0.f;

#pragma unroll
    for (int t = 0; t < 4; t++) {
      int idx = tid + 256 * t;
      int rr = idx >> 3, seg = idx & 7;
      size_t gsrc = ((((size_t)bh << 10) + i0 + rr) << 10) + seg * 8;
      cp16(smd + rr * LDSTRIDE + seg * 8, g_attn_h + gsrc);
    }
#pragma unroll
    for (int t = 0; t < 2; t++) {
      int idx = tid + 256 * t;
      int d = idx >> 3, seg = idx & 7;
      int so = AV_A + d * LDSTRIDE + seg * 8;
      cp16(smd + so, vth + (size_t)d * 1024 + seg * 8);
      cp16(smd + AV_V + so, vtl + (size_t)d * 1024 + seg * 8);
    }
    CP_COMMIT();

    for (int ck = 0; ck < 16; ck++) {
      int st = ck & 1;
      if (ck < 15) {
        int sn = st ^ 1;
        __nv_bfloat16* base = smd + sn * AV_STAGE;
#pragma unroll
        for (int t = 0; t < 4; t++) {
          int idx = tid + 256 * t;
          int rr = idx >> 3, seg = idx & 7;
          size_t gsrc = ((((size_t)bh << 10) + i0 + rr) << 10) + (ck + 1) * 64 + seg * 8;
          cp16(base + rr * LDSTRIDE + seg * 8, g_attn_h + gsrc);
        }
#pragma unroll
        for (int t = 0; t < 2; t++) {
          int idx = tid + 256 * t;
          int d = idx >> 3, seg = idx & 7;
          int so = AV_A + d * LDSTRIDE + seg * 8;
          cp16(base + so, vth + (size_t)d * 1024 + (ck + 1) * 64 + seg * 8);
          cp16(base + AV_V + so, vtl + (size_t)d * 1024 + (ck + 1) * 64 + seg * 8);
        }
        CP_COMMIT();
        CP_WAIT1();
      } else {
        CP_WAIT0();
      }
      __syncthreads();
      const __nv_bfloat16* AHs = smd + st * AV_STAGE;
      const __nv_bfloat16* VHs = AHs + AV_A;
      const __nv_bfloat16* VLs = VHs + AV_V;

#pragma unroll
      for (int kb = 0; kb < 64; kb += 16) {
        uint32_t ah[2][4];
#pragma unroll
        for (int mt = 0; mt < 2; mt++)
          ldsm4(ah[mt], AHs + (m_w + mt * 16 + (g & 1) * 8 + rw) * LDSTRIDE + kb + (g >> 1) * 8);
        uint32_t bh4[2][4], bl4[2][4];
#pragma unroll
        for (int p = 0; p < 2; p++) {
          ldsm4(bh4[p], VHs + (n_w + p * 16 + (g >> 1) * 8 + rw) * LDSTRIDE + kb + (g & 1) * 8);
          ldsm4(bl4[p], VLs + (n_w + p * 16 + (g >> 1) * 8 + rw) * LDSTRIDE + kb + (g & 1) * 8);
        }
#pragma unroll
        for (int mt = 0; mt < 2; mt++)
#pragma unroll
          for (int p = 0; p < 2; p++) {
            mma16816(c[mt][2 * p], ah[mt], bh4[p]);
            mma16816(c[mt][2 * p], ah[mt], bl4[p]);
            mma16816(c[mt][2 * p + 1], ah[mt], bh4[p] + 2);
            mma16816(c[mt][2 * p + 1], ah[mt], bl4[p] + 2);
          }
      }
      __syncthreads();
    }

#pragma unroll
    for (int mt = 0; mt < 2; mt++) {
#pragma unroll
      for (int nt = 0; nt < 4; nt++) {
        int row = i0 + m_w + mt * 16 + r;
        int col = n_w + nt * 8 + (lane & 3) * 2;
        float* dst = g_oh + ((size_t)bh * 1024 + row) * 64 + col;
        *(float2*)dst = make_float2(c[mt][nt][0], c[mt][nt][1]);
        *(float2*)(dst + 8 * 64) = make_float2(c[mt][nt][2], c[mt][nt][3]);
      }
    }
  } else {
    // =================== PES body ===================
    int i = blockIdx.x - 256;
    // layout: AH stage0, AH stage1, PH stage0, PH stage1 (each 32*PSTRIDE)
    __nv_bfloat16* AH0 = smd;
    __nv_bfloat16* PH0 = smd + 2 * 32 * PSTRIDE;

    int mw = (wid & 1) * 16;        // bh rows
    int nw = (wid >> 1) * 8;        // c cols
    int r = lane >> 2, kq = (lane & 3) * 2;

    // prefetch attn chunk 0 via cp.async
#pragma unroll
    for (int t = 0; t < 2; t++) {
      int idx = tid + 256 * t;
      int row = idx >> 4, seg = idx & 15;
      size_t gsrc = ((size_t)row << 20) + ((size_t)i << 10) + seg * 8;
      cp16(AH0 + row * PSTRIDE + seg * 8, g_attn_h + gsrc);
    }
    CP_COMMIT();
    // preload pe chunk 0 into registers
    float4 pv[4];
#pragma unroll
    for (int t = 0; t < 4; t++) {
      int idx = tid + 256 * t;
      int j = idx >> 3, c4 = idx & 7;
      pv[t] = *(const float4*)(pe + (((size_t)i << 10) + j) * 32 + c4 * 4);
    }

    float acc[4] = {};
    for (int kc = 0; kc < 8; kc++) {
      int st = kc & 1;
      if (kc < 7) {
        __nv_bfloat16* AHn = AH0 + (st ^ 1) * 32 * PSTRIDE;
#pragma unroll
        for (int t = 0; t < 2; t++) {
          int idx = tid + 256 * t;
          int row = idx >> 4, seg = idx & 15;
          size_t gsrc = ((size_t)row << 20) + ((size_t)i << 10) + (kc + 1) * 128 + seg * 8;
          cp16(AHn + row * PSTRIDE + seg * 8, g_attn_h + gsrc);
        }
        CP_COMMIT();
      }
      // store prefetched pe regs to PH[st] transposed (bf16)
      __nv_bfloat16* PHs = PH0 + st * 32 * PSTRIDE;
#pragma unroll
      for (int t = 0; t < 4; t++) {
        int idx = tid + 256 * t;
        int j = idx >> 3, c4 = idx & 7;
        PHs[(c4 * 4 + 0) * PSTRIDE + j] = __float2bfloat16_rn(pv[t].x);
        PHs[(c4 * 4 + 1) * PSTRIDE + j] = __float2bfloat16_rn(pv[t].y);
        PHs[(c4 * 4 + 2) * PSTRIDE + j] = __float2bfloat16_rn(pv[t].z);
        PHs[(c4 * 4 + 3) * PSTRIDE + j] = __float2bfloat16_rn(pv[t].w);
      }
      // preload next pe chunk (latency hidden behind mma)
      if (kc < 7) {
#pragma unroll
        for (int t = 0; t < 4; t++) {
          int idx = tid + 256 * t;
          int j = idx >> 3, c4 = idx & 7;
          pv[t] = *(const float4*)(
              pe + (((size_t)i << 10) + (kc + 1) * 128 + j) * 32 + c4 * 4);
        }
      }
      if (kc < 7) CP_WAIT1(); else CP_WAIT0();
      __syncthreads();
      const __nv_bfloat16* AHs = AH0 + st * 32 * PSTRIDE;
#pragma unroll
      for (int kb = 0; kb < 8; kb++) {
        const __nv_bfloat16* p = AHs + (mw + r) * PSTRIDE + kb * 16 + kq;
        uint32_t ah4[4] = {*(const uint32_t*)p,
                           *(const uint32_t*)(p + 8 * PSTRIDE),
                           *(const uint32_t*)(p + 8),
                           *(const uint32_t*)(p + 8 * PSTRIDE + 8)};
        const __nv_bfloat16* pb = PHs + (nw + r) * PSTRIDE + kb * 16 + kq;
        uint32_t bh2[2] = {*(const uint32_t*)pb, *(const uint32_t*)(pb + 8)};
        mma16816(acc, ah4, bh2);
      }
      __syncthreads();
    }
    int c = nw + (lane & 3) * 2;
    int b0 = mw + r, b1 = b0 + 8;
    *(float2*)&g_pes[(((size_t)b0 << 10) + i) * 32 + c] = make_float2(acc[0], acc[1]);
    *(float2*)&g_pes[(((size_t)b1 << 10) + i) * 32 + c] = make_float2(acc[2], acc[3]);
  }
}

// ---------------- Kernel 4: merged = out_head + pe_sum@Wpe + bpe (split) ----
__global__ __launch_bounds__(256) void merge_kernel(
    const float* __restrict__ Wpe, const float* __restrict__ bpe) {
  __shared__ float wpe_s[32 * 64];
  __shared__ float pes_s[32 * 32];
  __shared__ float bpe_s[64];
  int bh = blockIdx.x;
  int n0 = blockIdx.y * 32;
  int tid = threadIdx.x;
#pragma unroll
  for (int r = 0; r < 8; r++) wpe_s[tid + r * 256] = Wpe[tid + r * 256];
  if (tid < 64) bpe_s[tid] = bpe[tid];
  {
    int nl = tid >> 3, cc = tid & 7;
    *(float4*)&pes_s[nl * 32 + cc * 4] =
        *(const float4*)(g_pes + ((size_t)bh * 1024 + n0 + nl) * 32 + cc * 4);
  }
  __syncthreads();
  int nl = tid >> 3;
  int d0 = (tid & 7) * 8;
  int b = bh >> 3, h = bh & 7;
  const float* ohp = g_oh + ((size_t)bh * 1024 + n0 + nl) * 64 + d0;
  float o[8];
#pragma unroll
  for (int dd = 0; dd < 8; dd++) o[dd] = bpe_s[d0 + dd] + ohp[dd];
#pragma unroll 8
  for (int c = 0; c < 32; c++) {
    float pv = pes_s[nl * 32 + c];
#pragma unroll
    for (int dd = 0; dd < 8; dd++) o[dd] += pv * wpe_s[c * 64 + d0 + dd];
  }
  size_t mp = ((size_t)(b * 1024 + n0 + nl)) * 512 + h * 64 + d0;
  B16x8 hh, ll;
#pragma unroll
  for (int dd = 0; dd < 8; dd++) split2(o[dd], hh.h[dd], ll.h[dd]);
  *(uint4*)&g_mh[mp] = hh.u;
  *(uint4*)&g_ml[mp] = ll.u;
}

// ---------------- Kernel 5: out = merged @ Wproj via mma.sync ----------------
// M=4096, N=256, K=512. CTA 128m x 64n, grid (32, 4).
__global__ __launch_bounds__(256) void proj_mma(float* __restrict__ out) {
  extern __shared__ __nv_bfloat16 sm[];
  __nv_bfloat16* MH = sm;
  __nv_bfloat16* ML = MH + 128 * LDSTRIDE;
  __nv_bfloat16* WH = ML + 128 * LDSTRIDE;
  __nv_bfloat16* WL = WH + 64 * LDSTRIDE;

  int tid = threadIdx.x;
  int wid = tid >> 5, lane = tid & 31;
  int m0 = blockIdx.x * 128;
  int n0 = blockIdx.y * 64;

  int m_w = (wid >> 1) * 32, n_w = (wid & 1) * 32;
  int r = lane >> 2;
  int g = lane >> 3, rw = lane & 7;

  float c[2][4][4];
#pragma unroll
  for (int mt = 0; mt < 2; mt++)
#pragma unroll
    for (int nt = 0; nt < 4; nt++)
#pragma unroll
      for (int e = 0; e < 4; e++) c[mt][nt][e] = 0.f;

  for (int ck = 0; ck < 8; ck++) {
    if (ck) __syncthreads();
#pragma unroll
    for (int t = 0; t < 4; t++) {
      int idx = tid + 256 * t;
      int rr = idx >> 3, seg = idx & 7;
      int so = rr * LDSTRIDE + seg * 8;
      size_t gs = (size_t)(m0 + rr) * 512 + ck * 64 + seg * 8;
      *(uint4*)(MH + so) = *(const uint4*)(g_mh + gs);
      *(uint4*)(ML + so) = *(const uint4*)(g_ml + gs);
    }
#pragma unroll
    for (int t = 0; t < 2; t++) {
      int idx = tid + 256 * t;
      int d = idx >> 3, seg = idx & 7;
      int so = d * LDSTRIDE + seg * 8;
      size_t gs = (size_t)(n0 + d) * 512 + ck * 64 + seg * 8;
      *(uint4*)(WH + so) = *(const uint4*)(g_wpth + gs);
      *(uint4*)(WL + so) = *(const uint4*)(g_wptl + gs);
    }
    __syncthreads();
#pragma unroll
    for (int kb = 0; kb < 64; kb += 16) {
      uint32_t ah[2][4], al[2][4];
#pragma unroll
      for (int mt = 0; mt < 2; mt++) {
        ldsm4(ah[mt], MH + (m_w + mt * 16 + (g & 1) * 8 + rw) * LDSTRIDE + kb + (g >> 1) * 8);
        ldsm4(al[mt], ML + (m_w + mt * 16 + (g & 1) * 8 + rw) * LDSTRIDE + kb + (g >> 1) * 8);
      }
      uint32_t bh4[2][4], bl4[2][4];
#pragma unroll
      for (int p = 0; p < 2; p++) {
        ldsm4(bh4[p], WH + (n_w + p * 16 + (g >> 1) * 8 + rw) * LDSTRIDE + kb + (g & 1) * 8);
        ldsm4(bl4[p], WL + (n_w + p * 16 + (g >> 1) * 8 + rw) * LDSTRIDE + kb + (g & 1) * 8);
      }
#pragma unroll
      for (int mt = 0; mt < 2; mt++)
#pragma unroll
        for (int p = 0; p < 2; p++) {
          mma16816(c[mt][2 * p], ah[mt], bh4[p]);
          mma16816(c[mt][2 * p], ah[mt], bl4[p]);
          mma16816(c[mt][2 * p], al[mt], bh4[p]);
          mma16816(c[mt][2 * p + 1], ah[mt], bh4[p] + 2);
          mma16816(c[mt][2 * p + 1], ah[mt], bl4[p] + 2);
          mma16816(c[mt][2 * p + 1], al[mt], bh4[p] + 2);
        }
    }
  }

#pragma unroll
  for (int mt = 0; mt < 2; mt++) {
#pragma unroll
    for (int nt = 0; nt < 4; nt++) {
      int row = m0 + m_w + mt * 16 + r;
      int col = n0 + n_w + nt * 8 + (lane & 3) * 2;
      float* dst = out + (size_t)row * 256 + col;
      *(float2*)dst = make_float2(c[mt][nt][0], c[mt][nt][1]);
      *(float2*)(dst + 8 * 256) = make_float2(c[mt][nt][2], c[mt][nt][3]);
    }
  }
}

// ---------------- launch -----------------------------------------------------
extern "C" void kernel_launch(void* const* d_in, const int* in_sizes, int n_in,
                              void* d_out, int out_size) {
  const float* x     = (const float*)d_in[0];
  const float* pe    = (const float*)d_in[1];
  const float* Wq    = (const float*)d_in[2];
  const float* Wk    = (const float*)d_in[3];
  const float* Wv    = (const float*)d_in[4];
  const float* bv    = (const float*)d_in[5];
  const float* Wpe   = (const float*)d_in[6];
  const float* bpe   = (const float*)d_in[7];
  const float* Wproj = (const float*)d_in[8];
  float* out = (float*)d_out;

  cudaFuncSetAttribute(qkv_mma, cudaFuncAttributeMaxDynamicSharedMemorySize,
                       GEMM_SMEM_BYTES);
  cudaFuncSetAttribute(scoresm, cudaFuncAttributeMaxDynamicSharedMemorySize,
                       SM_SMEM_BYTES);
  cudaFuncSetAttribute(avpes, cudaFuncAttributeMaxDynamicSharedMemorySize,
                       AVP_SMEM_BYTES);
  cudaFuncSetAttribute(proj_mma, cudaFuncAttributeMaxDynamicSharedMemorySize,
                       GEMM_SMEM_BYTES);

  split_x<<<1024, 256>>>(x);
  prep_w<<<512, 256>>>(Wq, Wk, Wv, Wproj);
  qkv_mma<<<dim3(32, 24), 256, GEMM_SMEM_BYTES>>>(bv);
  scoresm<<<dim3(64, 32), 256, SM_SMEM_BYTES>>>();
  avpes<<<1280, 256, AVP_SMEM_BYTES>>>(pe);
  merge_kernel<<<dim3(32, 32), 256>>>(Wpe, bpe);
  proj_mma<<<dim3(32, 4), 256, GEMM_SMEM_BYTES>>>(out);
}